// round 8
// baseline (speedup 1.0000x reference)
#include <cuda_runtime.h>
#include <cuda_bf16.h>
#include <math.h>
#include <stdint.h>

// ---------------------------------------------------------------------------
// PerceiverResampler forward. Round 6:
//  - split-K for all M=512 GEMMs (partials + deterministic reduce)
//  - bvec as tiled reduction (was 80us serial), wtrans 64x64 tiles
//  - attn_combine writes bf16 hi/lo directly (cvt fused)
//  - big ctx-KV tgemm moved to launch index 5 (ncu -s 5 captures it)
// ---------------------------------------------------------------------------

#define BB 8
#define SS 4096
#define DIMM 1024
#define NL 64
#define NH 16
#define DH 64
#define HID 4096
#define ROWS_CTX (BB * SS)     // 32768
#define ROWS_LAT (BB * NL)     // 512
#define NSPLIT 9
#define QKV_STRIDE 3072
#define KVC_STRIDE 4096

// ------------------------- scratch (no allocations) ------------------------
#define OFF_PO      ((size_t)0)            // 4718592
#define OFF_PML     ((size_t)4718592)      // 147456
#define OFF_QKV     ((size_t)4866048)      // 1572864 (512x3072 f32)
#define OFF_AO      ((size_t)6438912)      // 524288 (unused f32, kept)
#define OFF_LAT     ((size_t)6963200)
#define OFF_LAT2    ((size_t)7487488)
#define OFF_H1      ((size_t)8011776)      // 2097152
#define OFF_LNL_HI  ((size_t)10108928)
#define OFF_LNL_LO  ((size_t)10371072)
#define OFF_AO_HI   ((size_t)10633216)
#define OFF_AO_LO   ((size_t)10895360)
#define OFF_H1_HI   ((size_t)11157504)     // 1048576
#define OFF_H1_LO   ((size_t)12206080)
#define OFF_BVEC    ((size_t)13254656)     // 4096
#define OFF_ZC_HI   ((size_t)13258752)     // 16777216
#define OFF_ZC_LO   ((size_t)30035968)
#define OFF_KVC     ((size_t)46813184)     // 134217728 (32768x4096 f32)
#define OFF_WKVC_HI ((size_t)181030912)    // 2097152
#define OFF_WKVC_LO ((size_t)183128064)
#define OFF_W       ((size_t)185225216)
#define WL_STRIDE   ((size_t)12582912)
#define WO_QKV_HI 0
#define WO_QKV_LO 1572864
#define WO_WO_HI  3145728
#define WO_WO_LO  3670016
#define WO_W1_HI  4194304
#define WO_W1_LO  6291456
#define WO_W2_HI  8388608
#define WO_W2_LO  10485760
#define OFF_PART    ((size_t)210391040)    // 6291456 (split-K partials)
#define SCRATCH_FLOATS ((size_t)216682496)

__device__ __align__(1024) float g_scratch[SCRATCH_FLOATS];

// ------------------------------ PTX helpers --------------------------------
__device__ __forceinline__ uint32_t smem_u32(const void* p) {
    uint32_t a;
    asm("{ .reg .u64 t; cvta.to.shared.u64 t, %1; cvt.u32.u64 %0, t; }"
        : "=r"(a) : "l"(p));
    return a;
}
__device__ __forceinline__ void cp16(uint32_t saddr, const void* g) {
    asm volatile("cp.async.cg.shared.global [%0], [%1], 16;"
                 :: "r"(saddr), "l"(g));
}
#define CP_COMMIT() asm volatile("cp.async.commit_group;" ::: "memory")
#define CP_WAIT0()  asm volatile("cp.async.wait_group 0;" ::: "memory")
#define CP_WAIT1()  asm volatile("cp.async.wait_group 1;" ::: "memory")

__device__ __forceinline__ void ldsm_x4(uint32_t& r0, uint32_t& r1,
                                        uint32_t& r2, uint32_t& r3,
                                        uint32_t addr) {
    asm volatile("ldmatrix.sync.aligned.m8n8.x4.shared.b16 {%0,%1,%2,%3}, [%4];"
                 : "=r"(r0), "=r"(r1), "=r"(r2), "=r"(r3) : "r"(addr));
}
__device__ __forceinline__ void mma_bf16(float& c0, float& c1, float& c2,
                                         float& c3, uint32_t a0, uint32_t a1,
                                         uint32_t a2, uint32_t a3,
                                         uint32_t b0, uint32_t b1) {
    asm volatile(
        "mma.sync.aligned.m16n8k16.row.col.f32.bf16.bf16.f32 "
        "{%0,%1,%2,%3}, {%4,%5,%6,%7}, {%8,%9}, {%0,%1,%2,%3};"
        : "+f"(c0), "+f"(c1), "+f"(c2), "+f"(c3)
        : "r"(a0), "r"(a1), "r"(a2), "r"(a3), "r"(b0), "r"(b1));
}
__device__ __forceinline__ uint32_t pk_hi(float x, float y) {
    __nv_bfloat162 t = __floats2bfloat162_rn(x, y);
    return *reinterpret_cast<uint32_t*>(&t);
}
__device__ __forceinline__ uint32_t pk_lo(float x, float y, uint32_t hi) {
    __nv_bfloat162 h = *reinterpret_cast<__nv_bfloat162*>(&hi);
    return pk_hi(x - __bfloat162float(h.x), y - __bfloat162float(h.y));
}

// --------------------------- latent broadcast ------------------------------
__global__ void initlat_kernel(const float* __restrict__ lat0,
                               float* __restrict__ lat) {
    int row = blockIdx.x;
    int l = row % NL;
    for (int d = threadIdx.x; d < DIMM; d += blockDim.x)
        lat[(size_t)row * DIMM + d] = lat0[(size_t)l * DIMM + d];
}

// ------------------------------- LayerNorm ---------------------------------
struct __align__(8) bf4 { __nv_bfloat16 v[4]; };

template <int POS, int OUT_BF16, int AFFINE>
__global__ void ln_kernel(const float* __restrict__ X,
                          const float* __restrict__ pos,
                          float* __restrict__ Yf,
                          __nv_bfloat16* __restrict__ Yhi,
                          __nv_bfloat16* __restrict__ Ylo,
                          const float* __restrict__ g,
                          const float* __restrict__ b) {
    const int row = blockIdx.x;
    const int tid = threadIdx.x;
    float4 v = ((const float4*)(X + (size_t)row * DIMM))[tid];
    if (POS) {
        float4 p = ((const float4*)(pos + (size_t)(row & (SS - 1)) * DIMM))[tid];
        v.x += p.x; v.y += p.y; v.z += p.z; v.w += p.w;
    }
    float s  = v.x + v.y + v.z + v.w;
    float s2 = v.x * v.x + v.y * v.y + v.z * v.z + v.w * v.w;

    __shared__ float red[2][8];
    for (int o = 16; o; o >>= 1) {
        s  += __shfl_xor_sync(0xffffffffu, s, o);
        s2 += __shfl_xor_sync(0xffffffffu, s2, o);
    }
    int w = tid >> 5;
    if ((tid & 31) == 0) { red[0][w] = s; red[1][w] = s2; }
    __syncthreads();
    if (tid < 32) {
        s  = (tid < 8) ? red[0][tid] : 0.f;
        s2 = (tid < 8) ? red[1][tid] : 0.f;
        for (int o = 4; o; o >>= 1) {
            s  += __shfl_xor_sync(0xffffffffu, s, o);
            s2 += __shfl_xor_sync(0xffffffffu, s2, o);
        }
        if (tid == 0) { red[0][0] = s; red[1][0] = s2; }
    }
    __syncthreads();
    float mean = red[0][0] * (1.0f / DIMM);
    float var  = red[1][0] * (1.0f / DIMM) - mean * mean;
    float rstd = rsqrtf(var + 1e-5f);

    float y0, y1, y2, y3;
    if (AFFINE) {
        float4 gv = ((const float4*)g)[tid];
        float4 bv = ((const float4*)b)[tid];
        y0 = (v.x - mean) * rstd * gv.x + bv.x;
        y1 = (v.y - mean) * rstd * gv.y + bv.y;
        y2 = (v.z - mean) * rstd * gv.z + bv.z;
        y3 = (v.w - mean) * rstd * gv.w + bv.w;
    } else {
        y0 = (v.x - mean) * rstd; y1 = (v.y - mean) * rstd;
        y2 = (v.z - mean) * rstd; y3 = (v.w - mean) * rstd;
    }
    if (OUT_BF16) {
        bf4 h, l;
        h.v[0] = __float2bfloat16(y0); l.v[0] = __float2bfloat16(y0 - __bfloat162float(h.v[0]));
        h.v[1] = __float2bfloat16(y1); l.v[1] = __float2bfloat16(y1 - __bfloat162float(h.v[1]));
        h.v[2] = __float2bfloat16(y2); l.v[2] = __float2bfloat16(y2 - __bfloat162float(h.v[2]));
        h.v[3] = __float2bfloat16(y3); l.v[3] = __float2bfloat16(y3 - __bfloat162float(h.v[3]));
        ((bf4*)(Yhi + (size_t)row * DIMM))[tid] = h;
        ((bf4*)(Ylo + (size_t)row * DIMM))[tid] = l;
    } else {
        ((float4*)(Yf + (size_t)row * DIMM))[tid] = make_float4(y0, y1, y2, y3);
    }
}

// ---------------------- gelu(exact) -> bf16 hi/lo --------------------------
__global__ void gelu_cvt_kernel(const float* __restrict__ X,
                                __nv_bfloat16* __restrict__ hi,
                                __nv_bfloat16* __restrict__ lo, int n) {
    for (int i = blockIdx.x * blockDim.x + threadIdx.x; i < n;
         i += gridDim.x * blockDim.x) {
        float v = X[i];
        float gl = 0.5f * v * (1.0f + erff(v * 0.70710678118654752f));
        __nv_bfloat16 h = __float2bfloat16(gl);
        hi[i] = h;
        lo[i] = __float2bfloat16(gl - __bfloat162float(h));
    }
}

// ------------------ weight transpose-convert: [K,N] -> [N,K] ----------------
// 64x64 tiles, block (64,4), 16 elems/thread.
template <int SCALED>
__global__ void wtrans_kernel(const float* __restrict__ W,
                              const float* __restrict__ gvec,
                              __nv_bfloat16* __restrict__ hi,
                              __nv_bfloat16* __restrict__ lo, int K, int N) {
    __shared__ float t[64][65];
    const int n0 = blockIdx.x * 64, k0 = blockIdx.y * 64;
    const int tx = threadIdx.x;   // 0..63
    const int ty = threadIdx.y;   // 0..3
#pragma unroll
    for (int r = ty; r < 64; r += 4)
        t[r][tx] = W[(size_t)(k0 + r) * N + n0 + tx];
    __syncthreads();
    const float gk = SCALED ? gvec[k0 + tx] : 1.0f;
#pragma unroll
    for (int r = ty; r < 64; r += 4) {
        float v = t[tx][r] * gk;               // W[k0+tx][n0+r] * g[k0+tx]
        size_t o = (size_t)(n0 + r) * K + k0 + tx;
        __nv_bfloat16 h = __float2bfloat16(v);
        hi[o] = h;
        lo[o] = __float2bfloat16(v - __bfloat162float(h));
    }
}

// ------------- bias rows (both layers): bvec[l][n] = sum_k b[l][k]*Wkv[l][k][n]
__global__ void bvec_kernel(const float* __restrict__ Wkv,
                            const float* __restrict__ ln_x_b,
                            float* __restrict__ out) {
    // grid 128: layer = bid>>6, n-block = bid&63 (32 cols). block (32,8).
    const int layer = blockIdx.x >> 6;
    const int n0 = (blockIdx.x & 63) * 32;
    const float* W = Wkv + (size_t)layer * DIMM * 2048;
    const float* b = ln_x_b + layer * DIMM;
    const int tx = threadIdx.x, ty = threadIdx.y;
    float acc = 0.f;
    for (int k = ty; k < DIMM; k += 8)
        acc += b[k] * W[(size_t)k * 2048 + n0 + tx];
    __shared__ float red[8][33];
    red[ty][tx] = acc;
    __syncthreads();
    if (ty == 0) {
        float s = 0.f;
#pragma unroll
        for (int r = 0; r < 8; r++) s += red[r][tx];
        out[layer * 2048 + n0 + tx] = s;
    }
}

// ------------------------- HMMA GEMM (mma.sync bf16) -----------------------
// 128x128 tile, Kc=32, 3-stage cp.async, 96KB smem, 2 CTAs/SM.
// Split-K via gridDim.z: each z handles K/S slice, writes C + z*M*N (MODE 0).
#define TG_SMEM 98304

__device__ __forceinline__ void tg_load_stage32(
    uint32_t sb, const __nv_bfloat16* a_hi, const __nv_bfloat16* a_lo,
    const __nv_bfloat16* b_hi, const __nv_bfloat16* b_lo,
    int m0, int n0, int kc, int K, int tid) {
#pragma unroll
    for (int i = 0; i < 2; i++) {
        int idx = tid + i * 256;
        int r = idx >> 2, g = idx & 3;
        uint32_t off = (uint32_t)(r * 64 + ((g ^ (r & 3)) * 16));
        size_t ar = (size_t)(m0 + r) * K + kc + g * 8;
        size_t br = (size_t)(n0 + r) * K + kc + g * 8;
        cp16(sb + off,         a_hi + ar);
        cp16(sb + 8192 + off,  a_lo + ar);
        cp16(sb + 16384 + off, b_hi + br);
        cp16(sb + 24576 + off, b_lo + br);
    }
}

template <int MODE>
__global__ __launch_bounds__(256, 2)
void tgemm_kernel(const __nv_bfloat16* __restrict__ a_hi,
                  const __nv_bfloat16* __restrict__ a_lo,
                  const __nv_bfloat16* __restrict__ b_hi,
                  const __nv_bfloat16* __restrict__ b_lo,
                  float* __restrict__ C,
                  const float* __restrict__ bias,
                  const float* __restrict__ res,
                  int M, int N, int K) {
    extern __shared__ __align__(128) char dsm[];
    const uint32_t sbase = smem_u32(dsm);

    const int tid = threadIdx.x;
    const int lane = tid & 31;
    const int wid = tid >> 5;
    const int wm = wid >> 2;
    const int wn = wid & 3;
    const int m0 = blockIdx.y * 128;
    const int n0 = blockIdx.x * 128;
    const int Ks = K / (int)gridDim.z;
    const int koff = blockIdx.z * Ks;
    float* Cz = C + (size_t)blockIdx.z * M * N;

    const int lr = (lane & 7) + ((lane >> 3) & 1) * 8;
    const int gl = lane >> 4;
    const int rA = wm * 64 + lr;
    const int rB = wn * 32 + lr;
    const uint32_t baseA = (uint32_t)(rA * 64);
    const uint32_t baseB = (uint32_t)(rB * 64);
    const int xA = rA & 3, xB = rB & 3;

    float acc[4][4][4];
#pragma unroll
    for (int i = 0; i < 4; i++)
#pragma unroll
        for (int j = 0; j < 4; j++)
#pragma unroll
            for (int t = 0; t < 4; t++) acc[i][j][t] = 0.f;

    const int nc = Ks >> 5;
    tg_load_stage32(sbase, a_hi, a_lo, b_hi, b_lo, m0, n0, koff, K, tid);
    CP_COMMIT();
    tg_load_stage32(sbase + 32768, a_hi, a_lo, b_hi, b_lo, m0, n0, koff + 32, K, tid);
    CP_COMMIT();
    CP_WAIT1();
    __syncthreads();

    int stage = 0;
    for (int c = 0; c < nc; c++) {
        const uint32_t sb = sbase + stage * 32768;
        if (c + 2 < nc) {
            int ns = stage + 2; if (ns >= 3) ns -= 3;
            tg_load_stage32(sbase + ns * 32768, a_hi, a_lo, b_hi, b_lo,
                            m0, n0, koff + ((c + 2) << 5), K, tid);
        }
        CP_COMMIT();
#pragma unroll
        for (int ks = 0; ks < 2; ks++) {
            const uint32_t kgA = (uint32_t)(((ks * 2 + gl) ^ xA) * 16);
            const uint32_t kgB = (uint32_t)(((ks * 2 + gl) ^ xB) * 16);
            uint32_t fa[4][4], fbh[2][4], fbl[2][4];
#pragma unroll
            for (int i = 0; i < 4; i++)
                ldsm_x4(fa[i][0], fa[i][1], fa[i][2], fa[i][3],
                        sb + baseA + i * 1024 + kgA);
#pragma unroll
            for (int jj = 0; jj < 2; jj++) {
                uint32_t bd = sb + 16384 + baseB + jj * 1024 + kgB;
                ldsm_x4(fbh[jj][0], fbh[jj][1], fbh[jj][2], fbh[jj][3], bd);
                ldsm_x4(fbl[jj][0], fbl[jj][1], fbl[jj][2], fbl[jj][3], bd + 8192);
            }
#pragma unroll
            for (int i = 0; i < 4; i++)
#pragma unroll
                for (int j = 0; j < 4; j++) {
                    const int jj = j >> 1, sel = j & 1;
                    mma_bf16(acc[i][j][0], acc[i][j][1], acc[i][j][2], acc[i][j][3],
                             fa[i][0], fa[i][1], fa[i][2], fa[i][3],
                             fbh[jj][sel], fbh[jj][sel + 2]);
                    mma_bf16(acc[i][j][0], acc[i][j][1], acc[i][j][2], acc[i][j][3],
                             fa[i][0], fa[i][1], fa[i][2], fa[i][3],
                             fbl[jj][sel], fbl[jj][sel + 2]);
                }
#pragma unroll
            for (int i = 0; i < 4; i++)
                ldsm_x4(fa[i][0], fa[i][1], fa[i][2], fa[i][3],
                        sb + 8192 + baseA + i * 1024 + kgA);
#pragma unroll
            for (int i = 0; i < 4; i++)
#pragma unroll
                for (int j = 0; j < 4; j++) {
                    const int jj = j >> 1, sel = j & 1;
                    mma_bf16(acc[i][j][0], acc[i][j][1], acc[i][j][2], acc[i][j][3],
                             fa[i][0], fa[i][1], fa[i][2], fa[i][3],
                             fbh[jj][sel], fbh[jj][sel + 2]);
                }
        }
        CP_WAIT1();
        __syncthreads();
        stage++; if (stage >= 3) stage = 0;
    }

#pragma unroll
    for (int i = 0; i < 4; i++) {
        const int row = m0 + wm * 64 + i * 16 + (lane >> 2);
#pragma unroll
        for (int j = 0; j < 4; j++) {
            const int col = n0 + wn * 32 + j * 8 + (lane & 3) * 2;
            float c0 = acc[i][j][0], c1 = acc[i][j][1];
            float c2 = acc[i][j][2], c3 = acc[i][j][3];
            if (MODE >= 1) {
                float b0 = bias[col], b1 = bias[col + 1];
                c0 += b0; c1 += b1; c2 += b0; c3 += b1;
            }
            if (MODE == 2) {
                const float* r0 = res + (size_t)row * N + col;
                const float* r1 = res + (size_t)(row + 8) * N + col;
                c0 += r0[0]; c1 += r0[1]; c2 += r1[0]; c3 += r1[1];
            }
            *(float2*)(Cz + (size_t)row * N + col)       = make_float2(c0, c1);
            *(float2*)(Cz + (size_t)(row + 8) * N + col) = make_float2(c2, c3);
        }
    }
}

// ---------------------- split-K reduce: C = sum(part) [+bias][+res] --------
template <int MODE, int S>
__global__ void kred_kernel(const float* __restrict__ part,
                            const float* __restrict__ bias,
                            const float* __restrict__ res,
                            float* __restrict__ C, int M, int N) {
    int idx = blockIdx.x * 256 + threadIdx.x;      // float4 index
    int tot = (M * N) >> 2;
    if (idx >= tot) return;
    const float4* p = (const float4*)part;
    size_t stride = (size_t)tot;
    float4 a = p[idx];
#pragma unroll
    for (int s = 1; s < S; s++) {
        float4 t = p[idx + s * stride];
        a.x += t.x; a.y += t.y; a.z += t.z; a.w += t.w;
    }
    if (MODE >= 1) {
        float4 bv = ((const float4*)bias)[idx % (N >> 2)];
        a.x += bv.x; a.y += bv.y; a.z += bv.z; a.w += bv.w;
    }
    if (MODE == 2) {
        float4 rv = ((const float4*)res)[idx];
        a.x += rv.x; a.y += rv.y; a.z += rv.z; a.w += rv.w;
    }
    ((float4*)C)[idx] = a;
}

// ---------------------- flash attention (HMMA, split-KV) --------------------
#define ATT_SMEM 49152

__global__ __launch_bounds__(128, 1)
void attn_kernel(const float* __restrict__ qkv,
                 const float* __restrict__ kvc_l,
                 const float* __restrict__ qn_g,
                 const float* __restrict__ kn_g,
                 float* __restrict__ po,
                 float2* __restrict__ pml) {
    extern __shared__ __align__(128) char asmem[];
    const uint32_t sq = smem_u32(asmem);
    const uint32_t sk = sq + 16384;
    const uint32_t sv = sq + 32768;

    const int h = blockIdx.x, b = blockIdx.y, split = blockIdx.z;
    const int tid = threadIdx.x, lane = tid & 31, w = tid >> 5;

    {
        const int qi = tid >> 1, half = tid & 1;
        const float* qrow = qkv + (size_t)(b * NL + qi) * QKV_STRIDE + h * DH + half * 32;
        float v[32]; float ss = 0.f;
#pragma unroll
        for (int i = 0; i < 32; i += 4) {
            float4 t = *(const float4*)(qrow + i);
            v[i] = t.x; v[i+1] = t.y; v[i+2] = t.z; v[i+3] = t.w;
            ss += t.x*t.x + t.y*t.y + t.z*t.z + t.w*t.w;
        }
        ss += __shfl_xor_sync(0xffffffffu, ss, 1);
        float sc = (1.0f / fmaxf(sqrtf(ss) * 0.125f, 1e-8f)) * 0.125f;
#pragma unroll
        for (int i = 0; i < 32; i++) v[i] *= sc * qn_g[half * 32 + i];
#pragma unroll
        for (int j = 0; j < 4; j++) {
            uint32_t ph[4], pl[4];
#pragma unroll
            for (int t = 0; t < 4; t++) {
                ph[t] = pk_hi(v[j*8 + t*2], v[j*8 + t*2 + 1]);
                pl[t] = pk_lo(v[j*8 + t*2], v[j*8 + t*2 + 1], ph[t]);
            }
            uint32_t off = (uint32_t)(qi * 128 + (((half * 4 + j) ^ (qi & 7)) * 16));
            *(uint4*)(asmem + off) = make_uint4(ph[0], ph[1], ph[2], ph[3]);
            *(uint4*)(asmem + 8192 + off) = make_uint4(pl[0], pl[1], pl[2], pl[3]);
        }
    }
    __syncthreads();

    const int lr = (lane & 7) + ((lane >> 3) & 1) * 8;
    const int gl = lane >> 4;
    const int rQ = w * 16 + lr;
    uint32_t qah[4][4], qal[4][4];
#pragma unroll
    for (int kt = 0; kt < 4; kt++) {
        uint32_t ad = sq + (uint32_t)(rQ * 128 + (((kt * 2 + gl) ^ (rQ & 7)) * 16));
        ldsm_x4(qah[kt][0], qah[kt][1], qah[kt][2], qah[kt][3], ad);
        ldsm_x4(qal[kt][0], qal[kt][1], qal[kt][2], qal[kt][3], ad + 8192);
    }

    float m0 = -INFINITY, m1 = -INFINITY, l0 = 0.f, l1 = 0.f;
    float o[8][4];
#pragma unroll
    for (int g = 0; g < 8; g++)
#pragma unroll
        for (int t = 0; t < 4; t++) o[g][t] = 0.f;

    const int nchunks = (split < 8) ? 8 : 1;
    for (int cc = 0; cc < nchunks; cc++) {
        {
            const int key = tid >> 1, half = tid & 1;
            const int j = split * 512 + cc * 64 + key;
            const float* base = (split < 8)
                ? kvc_l + (size_t)(b * SS + j) * KVC_STRIDE
                : qkv + (size_t)(b * NL + (j - SS)) * QKV_STRIDE + 1024;
            const float* kp = base + h * DH + half * 32;
            float v[32]; float ss = 0.f;
#pragma unroll
            for (int i = 0; i < 32; i += 4) {
                float4 t = *(const float4*)(kp + i);
                v[i] = t.x; v[i+1] = t.y; v[i+2] = t.z; v[i+3] = t.w;
                ss += t.x*t.x + t.y*t.y + t.z*t.z + t.w*t.w;
            }
            ss += __shfl_xor_sync(0xffffffffu, ss, 1);
            float inv = 1.0f / fmaxf(sqrtf(ss) * 0.125f, 1e-8f);
#pragma unroll
            for (int i = 0; i < 32; i++) v[i] *= inv * kn_g[half * 32 + i];
#pragma unroll
            for (int jg = 0; jg < 4; jg++) {
                uint32_t ph[4], pl[4];
#pragma unroll
                for (int t = 0; t < 4; t++) {
                    ph[t] = pk_hi(v[jg*8 + t*2], v[jg*8 + t*2 + 1]);
                    pl[t] = pk_lo(v[jg*8 + t*2], v[jg*8 + t*2 + 1], ph[t]);
                }
                uint32_t off = (uint32_t)(key * 128 + (((half * 4 + jg) ^ (key & 7)) * 16));
                *(uint4*)(asmem + 16384 + off) = make_uint4(ph[0], ph[1], ph[2], ph[3]);
                *(uint4*)(asmem + 24576 + off) = make_uint4(pl[0], pl[1], pl[2], pl[3]);
            }
            const float* vp = base + 1024 + h * DH + half * 32;
#pragma unroll
            for (int i = 0; i < 32; i++) {
                float vv = vp[i];
                int d = half * 32 + i;
                __nv_bfloat16 hh = __float2bfloat16(vv);
                __nv_bfloat16 ll = __float2bfloat16(vv - __bfloat162float(hh));
                uint32_t off = (uint32_t)(d * 128 + (((key >> 3) ^ (d & 7)) * 16)
                                          + (key & 7) * 2);
                *(__nv_bfloat16*)(asmem + 32768 + off) = hh;
                *(__nv_bfloat16*)(asmem + 40960 + off) = ll;
            }
        }
        __syncthreads();

        float s[8][4];
#pragma unroll
        for (int g = 0; g < 8; g++)
#pragma unroll
            for (int t = 0; t < 4; t++) s[g][t] = 0.f;
#pragma unroll
        for (int kt = 0; kt < 4; kt++) {
#pragma unroll
            for (int np = 0; np < 4; np++) {
                int rw = np * 16 + lr;
                uint32_t bd = sk + (uint32_t)(rw * 128 + (((kt*2+gl) ^ (rw & 7)) * 16));
                uint32_t hb[4], lb[4];
                ldsm_x4(hb[0], hb[1], hb[2], hb[3], bd);
                ldsm_x4(lb[0], lb[1], lb[2], lb[3], bd + 8192);
#pragma unroll
                for (int sub = 0; sub < 2; sub++) {
                    int ng = np * 2 + sub;
                    mma_bf16(s[ng][0], s[ng][1], s[ng][2], s[ng][3],
                             qah[kt][0], qah[kt][1], qah[kt][2], qah[kt][3],
                             hb[sub], hb[sub + 2]);
                    mma_bf16(s[ng][0], s[ng][1], s[ng][2], s[ng][3],
                             qah[kt][0], qah[kt][1], qah[kt][2], qah[kt][3],
                             lb[sub], lb[sub + 2]);
                    mma_bf16(s[ng][0], s[ng][1], s[ng][2], s[ng][3],
                             qal[kt][0], qal[kt][1], qal[kt][2], qal[kt][3],
                             hb[sub], hb[sub + 2]);
                }
            }
        }

        float cm0 = -INFINITY, cm1 = -INFINITY;
#pragma unroll
        for (int g = 0; g < 8; g++) {
            cm0 = fmaxf(cm0, fmaxf(s[g][0], s[g][1]));
            cm1 = fmaxf(cm1, fmaxf(s[g][2], s[g][3]));
        }
        cm0 = fmaxf(cm0, __shfl_xor_sync(0xffffffffu, cm0, 1));
        cm0 = fmaxf(cm0, __shfl_xor_sync(0xffffffffu, cm0, 2));
        cm1 = fmaxf(cm1, __shfl_xor_sync(0xffffffffu, cm1, 1));
        cm1 = fmaxf(cm1, __shfl_xor_sync(0xffffffffu, cm1, 2));
        float nm0 = fmaxf(m0, cm0), nm1 = fmaxf(m1, cm1);
        float a0 = __expf(m0 - nm0), a1 = __expf(m1 - nm1);
        float p[8][4]; float ls0 = 0.f, ls1 = 0.f;
#pragma unroll
        for (int g = 0; g < 8; g++) {
            p[g][0] = __expf(s[g][0] - nm0);
            p[g][1] = __expf(s[g][1] - nm0);
            p[g][2] = __expf(s[g][2] - nm1);
            p[g][3] = __expf(s[g][3] - nm1);
            ls0 += p[g][0] + p[g][1];
            ls1 += p[g][2] + p[g][3];
        }
        ls0 += __shfl_xor_sync(0xffffffffu, ls0, 1);
        ls0 += __shfl_xor_sync(0xffffffffu, ls0, 2);
        ls1 += __shfl_xor_sync(0xffffffffu, ls1, 1);
        ls1 += __shfl_xor_sync(0xffffffffu, ls1, 2);
        l0 = l0 * a0 + ls0; l1 = l1 * a1 + ls1;
        m0 = nm0; m1 = nm1;
#pragma unroll
        for (int g = 0; g < 8; g++) {
            o[g][0] *= a0; o[g][1] *= a0; o[g][2] *= a1; o[g][3] *= a1;
        }

#pragma unroll
        for (int kt = 0; kt < 4; kt++) {
            uint32_t pah[4], pal[4];
            pah[0] = pk_hi(p[2*kt][0],   p[2*kt][1]);
            pah[1] = pk_hi(p[2*kt][2],   p[2*kt][3]);
            pah[2] = pk_hi(p[2*kt+1][0], p[2*kt+1][1]);
            pah[3] = pk_hi(p[2*kt+1][2], p[2*kt+1][3]);
            pal[0] = pk_lo(p[2*kt][0],   p[2*kt][1],   pah[0]);
            pal[1] = pk_lo(p[2*kt][2],   p[2*kt][3],   pah[1]);
            pal[2] = pk_lo(p[2*kt+1][0], p[2*kt+1][1], pah[2]);
            pal[3] = pk_lo(p[2*kt+1][2], p[2*kt+1][3], pah[3]);
#pragma unroll
            for (int np = 0; np < 4; np++) {
                int rw = np * 16 + lr;
                uint32_t bd = sv + (uint32_t)(rw * 128 + (((kt*2+gl) ^ (rw & 7)) * 16));
                uint32_t hb[4], lb[4];
                ldsm_x4(hb[0], hb[1], hb[2], hb[3], bd);
                ldsm_x4(lb[0], lb[1], lb[2], lb[3], bd + 8192);
#pragma unroll
                for (int sub = 0; sub < 2; sub++) {
                    int ng = np * 2 + sub;
                    mma_bf16(o[ng][0], o[ng][1], o[ng][2], o[ng][3],
                             pah[0], pah[1], pah[2], pah[3], hb[sub], hb[sub + 2]);
                    mma_bf16(o[ng][0], o[ng][1], o[ng][2], o[ng][3],
                             pah[0], pah[1], pah[2], pah[3], lb[sub], lb[sub + 2]);
                    mma_bf16(o[ng][0], o[ng][1], o[ng][2], o[ng][3],
                             pal[0], pal[1], pal[2], pal[3], hb[sub], hb[sub + 2]);
                }
            }
        }
        __syncthreads();
    }

    const int row0 = w * 16 + (lane >> 2);
    const size_t pob = (size_t)((b * NH + h) * NSPLIT + split) * 4096;
#pragma unroll
    for (int g = 0; g < 8; g++) {
        int d0 = g * 8 + (lane & 3) * 2;
        *(float2*)(po + pob + (size_t)row0 * 64 + d0)       = make_float2(o[g][0], o[g][1]);
        *(float2*)(po + pob + (size_t)(row0 + 8) * 64 + d0) = make_float2(o[g][2], o[g][3]);
    }
    if ((lane & 3) == 0) {
        pml[((b * NH + h) * NSPLIT + split) * 64 + row0]     = make_float2(m0, l0);
        pml[((b * NH + h) * NSPLIT + split) * 64 + row0 + 8] = make_float2(m1, l1);
    }
}

// ---- combine split-KV partials; emit bf16 hi/lo directly ----
__global__ void attn_combine(const float* __restrict__ po,
                             const float2* __restrict__ pml,
                             __nv_bfloat16* __restrict__ ao_hi,
                             __nv_bfloat16* __restrict__ ao_lo) {
    const int bh = blockIdx.x;
    const int t = threadIdx.x;
    const int q = t >> 2, quad = t & 3;
    const int b = bh >> 4, h = bh & 15;

    float2 ml[NSPLIT];
    float M = -INFINITY;
#pragma unroll
    for (int s = 0; s < NSPLIT; s++) {
        ml[s] = pml[(bh * NSPLIT + s) * 64 + q];
        M = fmaxf(M, ml[s].x);
    }
    float L = 0.f; float wgt[NSPLIT];
#pragma unroll
    for (int s = 0; s < NSPLIT; s++) {
        wgt[s] = __expf(ml[s].x - M);
        L += ml[s].y * wgt[s];
    }
    float acc[16];
#pragma unroll
    for (int i = 0; i < 16; i++) acc[i] = 0.f;
#pragma unroll
    for (int s = 0; s < NSPLIT; s++) {
        const float* base = po + (size_t)(bh * NSPLIT + s) * 4096 + q * 64 + quad * 16;
#pragma unroll
        for (int i = 0; i < 4; i++) {
            float4 v = *(const float4*)(base + i * 4);
            acc[i*4+0] += wgt[s] * v.x; acc[i*4+1] += wgt[s] * v.y;
            acc[i*4+2] += wgt[s] * v.z; acc[i*4+3] += wgt[s] * v.w;
        }
    }
    float invL = 1.0f / L;
    size_t ob = (size_t)(b * NL + q) * DIMM + h * DH + quad * 16;
#pragma unroll
    for (int i = 0; i < 4; i++) {
        bf4 hh, ll;
#pragma unroll
        for (int e = 0; e < 4; e++) {
            float v = acc[i*4+e] * invL;
            hh.v[e] = __float2bfloat16(v);
            ll.v[e] = __float2bfloat16(v - __bfloat162float(hh.v[e]));
        }
        *(bf4*)(ao_hi + ob + i * 4) = hh;
        *(bf4*)(ao_lo + ob + i * 4) = ll;
    }
}

// ------------------------------- launcher ----------------------------------
extern "C" void kernel_launch(void* const* d_in, const int* in_sizes, int n_in,
                              void* d_out, int out_size) {
    const float* x       = (const float*)d_in[0];
    const float* pos     = (const float*)d_in[2];
    const float* lat0    = (const float*)d_in[3];
    const float* ln_x_g  = (const float*)d_in[4];
    const float* ln_x_b  = (const float*)d_in[5];
    const float* ln_l_g  = (const float*)d_in[6];
    const float* ln_l_b  = (const float*)d_in[7];
    const float* qn_g    = (const float*)d_in[8];
    const float* kn_g    = (const float*)d_in[9];
    const float* Wq      = (const float*)d_in[10];
    const float* Wkv     = (const float*)d_in[11];
    const float* Wo      = (const float*)d_in[12];
    const float* bo      = (const float*)d_in[13];
    const float* ff_ln_g = (const float*)d_in[14];
    const float* ff_ln_b = (const float*)d_in[15];
    const float* W1      = (const float*)d_in[16];
    const float* b1      = (const float*)d_in[17];
    const float* W2      = (const float*)d_in[18];
    const float* b2      = (const float*)d_in[19];
    const float* fn_g    = (const float*)d_in[20];
    const float* fn_b    = (const float*)d_in[21];

    cudaFuncSetAttribute(tgemm_kernel<0>,
                         cudaFuncAttributeMaxDynamicSharedMemorySize, TG_SMEM);
    cudaFuncSetAttribute(tgemm_kernel<1>,
                         cudaFuncAttributeMaxDynamicSharedMemorySize, TG_SMEM);
    cudaFuncSetAttribute(tgemm_kernel<2>,
                         cudaFuncAttributeMaxDynamicSharedMemorySize, TG_SMEM);
    cudaFuncSetAttribute(attn_kernel,
                         cudaFuncAttributeMaxDynamicSharedMemorySize, ATT_SMEM);

    float* scr = nullptr;
    cudaGetSymbolAddress((void**)&scr, g_scratch);
    float* po   = scr + OFF_PO;
    float2* pml = (float2*)(scr + OFF_PML);
    float* qkvl = scr + OFF_QKV;
    float* lat  = scr + OFF_LAT;
    float* lat2 = scr + OFF_LAT2;
    float* h1   = scr + OFF_H1;
    float* bvec = scr + OFF_BVEC;
    float* kvc  = scr + OFF_KVC;
    float* part = scr + OFF_PART;
    __nv_bfloat16* zc_hi   = (__nv_bfloat16*)(scr + OFF_ZC_HI);
    __nv_bfloat16* zc_lo   = (__nv_bfloat16*)(scr + OFF_ZC_LO);
    __nv_bfloat16* wkvc_hi = (__nv_bfloat16*)(scr + OFF_WKVC_HI);
    __nv_bfloat16* wkvc_lo = (__nv_bfloat16*)(scr + OFF_WKVC_LO);
    __nv_bfloat16* lnl_hi = (__nv_bfloat16*)(scr + OFF_LNL_HI);
    __nv_bfloat16* lnl_lo = (__nv_bfloat16*)(scr + OFF_LNL_LO);
    __nv_bfloat16* ao_hi  = (__nv_bfloat16*)(scr + OFF_AO_HI);
    __nv_bfloat16* ao_lo  = (__nv_bfloat16*)(scr + OFF_AO_LO);
    __nv_bfloat16* h1_hi  = (__nv_bfloat16*)(scr + OFF_H1_HI);
    __nv_bfloat16* h1_lo  = (__nv_bfloat16*)(scr + OFF_H1_LO);

    const dim3 wb(64, 4);
    const dim3 bvb(32, 8);

    // ---- launches 0..4: prerequisites of the big GEMM (ncu -s 5 lands on it)
    initlat_kernel<<<ROWS_LAT, 256>>>(lat0, lat);                           // 0
    ln_kernel<1, 1, 0><<<ROWS_CTX, 256>>>(x, pos, nullptr, zc_hi, zc_lo,
                                          nullptr, nullptr);                // 1
    for (int i = 0; i < 2; i++)                                             // 2,3
        wtrans_kernel<1><<<dim3(2 * DIMM / 64, DIMM / 64), wb>>>(
            Wkv + (size_t)i * DIMM * 2 * DIMM, ln_x_g + i * DIMM,
            wkvc_hi + (size_t)i * 2048 * 1024,
            wkvc_lo + (size_t)i * 2048 * 1024, DIMM, 2 * DIMM);
    bvec_kernel<<<128, bvb>>>(Wkv, ln_x_b, bvec);                           // 4

    // ---- launch 5: both layers' ctx KV in one GEMM: kvc[32768, 4096] ----
    tgemm_kernel<1><<<dim3(4096 / 128, ROWS_CTX / 128, 1), 256, TG_SMEM>>>(
        zc_hi, zc_lo, wkvc_hi, wkvc_lo, kvc, bvec, nullptr,
        ROWS_CTX, 4096, DIMM);

    // ---- remaining weight preprocessing ----
    for (int i = 0; i < 2; i++) {
        float* wl = scr + OFF_W + (size_t)i * WL_STRIDE;
        wtrans_kernel<0><<<dim3(DIMM / 64, DIMM / 64), wb>>>(
            Wq + (size_t)i * DIMM * DIMM, nullptr,
            (__nv_bfloat16*)(wl + WO_QKV_HI),
            (__nv_bfloat16*)(wl + WO_QKV_LO), DIMM, DIMM);
        wtrans_kernel<0><<<dim3(2 * DIMM / 64, DIMM / 64), wb>>>(
            Wkv + (size_t)i * DIMM * 2 * DIMM, nullptr,
            (__nv_bfloat16*)(wl + WO_QKV_HI) + (size_t)1024 * 1024,
            (__nv_bfloat16*)(wl + WO_QKV_LO) + (size_t)1024 * 1024,
            DIMM, 2 * DIMM);
        wtrans_kernel<0><<<dim3(DIMM / 64, DIMM / 64), wb>>>(
            Wo + (size_t)i * DIMM * DIMM, nullptr,
            (__nv_bfloat16*)(wl + WO_WO_HI), (__nv_bfloat16*)(wl + WO_WO_LO),
            DIMM, DIMM);
        wtrans_kernel<0><<<dim3(HID / 64, DIMM / 64), wb>>>(
            W1 + (size_t)i * DIMM * HID, nullptr,
            (__nv_bfloat16*)(wl + WO_W1_HI), (__nv_bfloat16*)(wl + WO_W1_LO),
            DIMM, HID);
        wtrans_kernel<0><<<dim3(DIMM / 64, HID / 64), wb>>>(
            W2 + (size_t)i * HID * DIMM, nullptr,
            (__nv_bfloat16*)(wl + WO_W2_HI), (__nv_bfloat16*)(wl + WO_W2_LO),
            HID, DIMM);
    }

    for (int i = 0; i < 2; i++) {
        float* wl = scr + OFF_W + (size_t)i * WL_STRIDE;
        __nv_bfloat16* wqkv_hi = (__nv_bfloat16*)(wl + WO_QKV_HI);
        __nv_bfloat16* wqkv_lo = (__nv_bfloat16*)(wl + WO_QKV_LO);
        __nv_bfloat16* wo_hi   = (__nv_bfloat16*)(wl + WO_WO_HI);
        __nv_bfloat16* wo_lo   = (__nv_bfloat16*)(wl + WO_WO_LO);
        __nv_bfloat16* w1_hi   = (__nv_bfloat16*)(wl + WO_W1_HI);
        __nv_bfloat16* w1_lo   = (__nv_bfloat16*)(wl + WO_W1_LO);
        __nv_bfloat16* w2_hi   = (__nv_bfloat16*)(wl + WO_W2_HI);
        __nv_bfloat16* w2_lo   = (__nv_bfloat16*)(wl + WO_W2_LO);

        ln_kernel<0, 1, 1><<<ROWS_LAT, 256>>>(lat, nullptr, nullptr,
                                              lnl_hi, lnl_lo,
                                              ln_l_g + i * DIMM, ln_l_b + i * DIMM);
        // fused q|latent-kv: split-K S=4 -> partials -> reduce
        tgemm_kernel<0><<<dim3(QKV_STRIDE / 128, ROWS_LAT / 128, 4), 256, TG_SMEM>>>(
            lnl_hi, lnl_lo, wqkv_hi, wqkv_lo, part, nullptr, nullptr,
            ROWS_LAT, QKV_STRIDE, DIMM);
        kred_kernel<0, 4><<<(ROWS_LAT * QKV_STRIDE / 4 + 255) / 256, 256>>>(
            part, nullptr, nullptr, qkvl, ROWS_LAT, QKV_STRIDE);

        attn_kernel<<<dim3(NH, BB, NSPLIT), 128, ATT_SMEM>>>(
            qkvl, kvc + (size_t)i * 2048, qn_g + i * DH, kn_g + i * DH, po, pml);
        attn_combine<<<BB * NH, 256>>>(po, pml, ao_hi, ao_lo);

        // Wo: split-K S=8, reduce adds bo + residual lat -> lat2
        tgemm_kernel<0><<<dim3(DIMM / 128, ROWS_LAT / 128, 8), 256, TG_SMEM>>>(
            ao_hi, ao_lo, wo_hi, wo_lo, part, nullptr, nullptr,
            ROWS_LAT, DIMM, DIMM);
        kred_kernel<2, 8><<<(ROWS_LAT * DIMM / 4 + 255) / 256, 256>>>(
            part, bo + i * DIMM, lat, lat2, ROWS_LAT, DIMM);

        ln_kernel<0, 1, 1><<<ROWS_LAT, 256>>>(lat2, nullptr, nullptr,
                                              lnl_hi, lnl_lo,
                                              ff_ln_g + i * DIMM, ff_ln_b + i * DIMM);
        // W1: split-K S=2, reduce adds b1 -> h1
        tgemm_kernel<0><<<dim3(HID / 128, ROWS_LAT / 128, 2), 256, TG_SMEM>>>(
            lnl_hi, lnl_lo, w1_hi, w1_lo, part, nullptr, nullptr,
            ROWS_LAT, HID, DIMM);
        kred_kernel<1, 2><<<(ROWS_LAT * HID / 4 + 255) / 256, 256>>>(
            part, b1 + i * HID, nullptr, h1, ROWS_LAT, HID);

        gelu_cvt_kernel<<<2048, 256>>>(h1, h1_hi, h1_lo, ROWS_LAT * HID);

        // W2: split-K S=8 (K=4096), reduce adds b2 + residual lat2 -> lat
        tgemm_kernel<0><<<dim3(DIMM / 128, ROWS_LAT / 128, 8), 256, TG_SMEM>>>(
            h1_hi, h1_lo, w2_hi, w2_lo, part, nullptr, nullptr,
            ROWS_LAT, DIMM, HID);
        kred_kernel<2, 8><<<(ROWS_LAT * DIMM / 4 + 255) / 256, 256>>>(
            part, b2 + i * DIMM, lat2, lat, ROWS_LAT, DIMM);
    }

    ln_kernel<0, 0, 1><<<ROWS_LAT, 256>>>(lat, nullptr, (float*)d_out,
                                          nullptr, nullptr, fn_g, fn_b);
}

// round 9
// speedup vs baseline: 1.6379x; 1.6379x over previous
#include <cuda_runtime.h>
#include <cuda_bf16.h>
#include <cuda_fp16.h>
#include <math.h>
#include <stdint.h>

// ---------------------------------------------------------------------------
// PerceiverResampler forward. Round 8:
//  - REVERT split-K (regression); base = round-5 structure
//  - big ctx-KV GEMM -> fp16 2-term (A exact hi/lo fp16 split, B single fp16)
//  - tiled bvec (one launch), fused bf16 attn_combine, 64x64 wtrans
// ---------------------------------------------------------------------------

#define BB 8
#define SS 4096
#define DIMM 1024
#define NL 64
#define NH 16
#define DH 64
#define HID 4096
#define ROWS_CTX (BB * SS)     // 32768
#define ROWS_LAT (BB * NL)     // 512
#define NSPLIT 9
#define QKV_STRIDE 3072
#define KVC_STRIDE 4096

// ------------------------- scratch (no allocations) ------------------------
#define OFF_PO      ((size_t)0)
#define OFF_PML     ((size_t)4718592)
#define OFF_QKV     ((size_t)4866048)
#define OFF_LAT     ((size_t)6963200)
#define OFF_LAT2    ((size_t)7487488)
#define OFF_H1      ((size_t)8011776)
#define OFF_LNL_HI  ((size_t)10108928)
#define OFF_LNL_LO  ((size_t)10371072)
#define OFF_AO_HI   ((size_t)10633216)
#define OFF_AO_LO   ((size_t)10895360)
#define OFF_H1_HI   ((size_t)11157504)
#define OFF_H1_LO   ((size_t)12206080)
#define OFF_BVEC    ((size_t)13254656)
#define OFF_ZC_HI   ((size_t)13258752)     // 32768x1024 fp16 (64MB)
#define OFF_ZC_LO   ((size_t)30035968)
#define OFF_KVC     ((size_t)46813184)     // 32768x4096 f32
#define OFF_WKVC16  ((size_t)181030912)    // 2x(2048x1024) fp16
#define OFF_W       ((size_t)185225216)
#define WL_STRIDE   ((size_t)12582912)
#define WO_QKV_HI 0
#define WO_QKV_LO 1572864
#define WO_WO_HI  3145728
#define WO_WO_LO  3670016
#define WO_W1_HI  4194304
#define WO_W1_LO  6291456
#define WO_W2_HI  8388608
#define WO_W2_LO  10485760
#define SCRATCH_FLOATS ((size_t)210391040)

__device__ __align__(1024) float g_scratch[SCRATCH_FLOATS];

// ------------------------------ PTX helpers --------------------------------
__device__ __forceinline__ uint32_t smem_u32(const void* p) {
    uint32_t a;
    asm("{ .reg .u64 t; cvta.to.shared.u64 t, %1; cvt.u32.u64 %0, t; }"
        : "=r"(a) : "l"(p));
    return a;
}
__device__ __forceinline__ void cp16(uint32_t saddr, const void* g) {
    asm volatile("cp.async.cg.shared.global [%0], [%1], 16;"
                 :: "r"(saddr), "l"(g));
}
#define CP_COMMIT() asm volatile("cp.async.commit_group;" ::: "memory")
#define CP_WAIT0()  asm volatile("cp.async.wait_group 0;" ::: "memory")
#define CP_WAIT1()  asm volatile("cp.async.wait_group 1;" ::: "memory")

__device__ __forceinline__ void ldsm_x4(uint32_t& r0, uint32_t& r1,
                                        uint32_t& r2, uint32_t& r3,
                                        uint32_t addr) {
    asm volatile("ldmatrix.sync.aligned.m8n8.x4.shared.b16 {%0,%1,%2,%3}, [%4];"
                 : "=r"(r0), "=r"(r1), "=r"(r2), "=r"(r3) : "r"(addr));
}
__device__ __forceinline__ void mma_bf16(float& c0, float& c1, float& c2,
                                         float& c3, uint32_t a0, uint32_t a1,
                                         uint32_t a2, uint32_t a3,
                                         uint32_t b0, uint32_t b1) {
    asm volatile(
        "mma.sync.aligned.m16n8k16.row.col.f32.bf16.bf16.f32 "
        "{%0,%1,%2,%3}, {%4,%5,%6,%7}, {%8,%9}, {%0,%1,%2,%3};"
        : "+f"(c0), "+f"(c1), "+f"(c2), "+f"(c3)
        : "r"(a0), "r"(a1), "r"(a2), "r"(a3), "r"(b0), "r"(b1));
}
__device__ __forceinline__ void mma_f16(float& c0, float& c1, float& c2,
                                        float& c3, uint32_t a0, uint32_t a1,
                                        uint32_t a2, uint32_t a3,
                                        uint32_t b0, uint32_t b1) {
    asm volatile(
        "mma.sync.aligned.m16n8k16.row.col.f32.f16.f16.f32 "
        "{%0,%1,%2,%3}, {%4,%5,%6,%7}, {%8,%9}, {%0,%1,%2,%3};"
        : "+f"(c0), "+f"(c1), "+f"(c2), "+f"(c3)
        : "r"(a0), "r"(a1), "r"(a2), "r"(a3), "r"(b0), "r"(b1));
}
__device__ __forceinline__ uint32_t pk_hi(float x, float y) {
    __nv_bfloat162 t = __floats2bfloat162_rn(x, y);
    return *reinterpret_cast<uint32_t*>(&t);
}
__device__ __forceinline__ uint32_t pk_lo(float x, float y, uint32_t hi) {
    __nv_bfloat162 h = *reinterpret_cast<__nv_bfloat162*>(&hi);
    return pk_hi(x - __bfloat162float(h.x), y - __bfloat162float(h.y));
}

// --------------------------- latent broadcast ------------------------------
__global__ void initlat_kernel(const float* __restrict__ lat0,
                               float* __restrict__ lat) {
    int row = blockIdx.x;
    int l = row % NL;
    for (int d = threadIdx.x; d < DIMM; d += blockDim.x)
        lat[(size_t)row * DIMM + d] = lat0[(size_t)l * DIMM + d];
}

// ------------------------------- LayerNorm ---------------------------------
struct __align__(8) bf4 { __nv_bfloat16 v[4]; };
struct __align__(8) hf4 { __half v[4]; };

template <int POS, int OUT_BF16, int AFFINE>
__global__ void ln_kernel(const float* __restrict__ X,
                          const float* __restrict__ pos,
                          float* __restrict__ Yf,
                          __nv_bfloat16* __restrict__ Yhi,
                          __nv_bfloat16* __restrict__ Ylo,
                          const float* __restrict__ g,
                          const float* __restrict__ b) {
    const int row = blockIdx.x;
    const int tid = threadIdx.x;
    float4 v = ((const float4*)(X + (size_t)row * DIMM))[tid];
    if (POS) {
        float4 p = ((const float4*)(pos + (size_t)(row & (SS - 1)) * DIMM))[tid];
        v.x += p.x; v.y += p.y; v.z += p.z; v.w += p.w;
    }
    float s  = v.x + v.y + v.z + v.w;
    float s2 = v.x * v.x + v.y * v.y + v.z * v.z + v.w * v.w;

    __shared__ float red[2][8];
    for (int o = 16; o; o >>= 1) {
        s  += __shfl_xor_sync(0xffffffffu, s, o);
        s2 += __shfl_xor_sync(0xffffffffu, s2, o);
    }
    int w = tid >> 5;
    if ((tid & 31) == 0) { red[0][w] = s; red[1][w] = s2; }
    __syncthreads();
    if (tid < 32) {
        s  = (tid < 8) ? red[0][tid] : 0.f;
        s2 = (tid < 8) ? red[1][tid] : 0.f;
        for (int o = 4; o; o >>= 1) {
            s  += __shfl_xor_sync(0xffffffffu, s, o);
            s2 += __shfl_xor_sync(0xffffffffu, s2, o);
        }
        if (tid == 0) { red[0][0] = s; red[1][0] = s2; }
    }
    __syncthreads();
    float mean = red[0][0] * (1.0f / DIMM);
    float var  = red[1][0] * (1.0f / DIMM) - mean * mean;
    float rstd = rsqrtf(var + 1e-5f);

    float y0, y1, y2, y3;
    if (AFFINE) {
        float4 gv = ((const float4*)g)[tid];
        float4 bv = ((const float4*)b)[tid];
        y0 = (v.x - mean) * rstd * gv.x + bv.x;
        y1 = (v.y - mean) * rstd * gv.y + bv.y;
        y2 = (v.z - mean) * rstd * gv.z + bv.z;
        y3 = (v.w - mean) * rstd * gv.w + bv.w;
    } else {
        y0 = (v.x - mean) * rstd; y1 = (v.y - mean) * rstd;
        y2 = (v.z - mean) * rstd; y3 = (v.w - mean) * rstd;
    }
    if (OUT_BF16) {
        bf4 h, l;
        h.v[0] = __float2bfloat16(y0); l.v[0] = __float2bfloat16(y0 - __bfloat162float(h.v[0]));
        h.v[1] = __float2bfloat16(y1); l.v[1] = __float2bfloat16(y1 - __bfloat162float(h.v[1]));
        h.v[2] = __float2bfloat16(y2); l.v[2] = __float2bfloat16(y2 - __bfloat162float(h.v[2]));
        h.v[3] = __float2bfloat16(y3); l.v[3] = __float2bfloat16(y3 - __bfloat162float(h.v[3]));
        ((bf4*)(Yhi + (size_t)row * DIMM))[tid] = h;
        ((bf4*)(Ylo + (size_t)row * DIMM))[tid] = l;
    } else {
        ((float4*)(Yf + (size_t)row * DIMM))[tid] = make_float4(y0, y1, y2, y3);
    }
}

// ---- ctx LN with pos add, NO affine, fp16 hi/lo (exact 2-split) output ----
__global__ void lnz_kernel(const float* __restrict__ X,
                           const float* __restrict__ pos,
                           __half* __restrict__ Yhi,
                           __half* __restrict__ Ylo) {
    const int row = blockIdx.x;
    const int tid = threadIdx.x;
    float4 v = ((const float4*)(X + (size_t)row * DIMM))[tid];
    float4 p = ((const float4*)(pos + (size_t)(row & (SS - 1)) * DIMM))[tid];
    v.x += p.x; v.y += p.y; v.z += p.z; v.w += p.w;
    float s  = v.x + v.y + v.z + v.w;
    float s2 = v.x * v.x + v.y * v.y + v.z * v.z + v.w * v.w;

    __shared__ float red[2][8];
    for (int o = 16; o; o >>= 1) {
        s  += __shfl_xor_sync(0xffffffffu, s, o);
        s2 += __shfl_xor_sync(0xffffffffu, s2, o);
    }
    int w = tid >> 5;
    if ((tid & 31) == 0) { red[0][w] = s; red[1][w] = s2; }
    __syncthreads();
    if (tid < 32) {
        s  = (tid < 8) ? red[0][tid] : 0.f;
        s2 = (tid < 8) ? red[1][tid] : 0.f;
        for (int o = 4; o; o >>= 1) {
            s  += __shfl_xor_sync(0xffffffffu, s, o);
            s2 += __shfl_xor_sync(0xffffffffu, s2, o);
        }
        if (tid == 0) { red[0][0] = s; red[1][0] = s2; }
    }
    __syncthreads();
    float mean = red[0][0] * (1.0f / DIMM);
    float var  = red[1][0] * (1.0f / DIMM) - mean * mean;
    float rstd = rsqrtf(var + 1e-5f);

    float y[4] = {(v.x - mean) * rstd, (v.y - mean) * rstd,
                  (v.z - mean) * rstd, (v.w - mean) * rstd};
    hf4 h, l;
#pragma unroll
    for (int e = 0; e < 4; e++) {
        h.v[e] = __float2half(y[e]);
        l.v[e] = __float2half(y[e] - __half2float(h.v[e]));
    }
    ((hf4*)(Yhi + (size_t)row * DIMM))[tid] = h;
    ((hf4*)(Ylo + (size_t)row * DIMM))[tid] = l;
}

// ---------------------- gelu(exact) -> bf16 hi/lo --------------------------
__global__ void gelu_cvt_kernel(const float* __restrict__ X,
                                __nv_bfloat16* __restrict__ hi,
                                __nv_bfloat16* __restrict__ lo, int n) {
    for (int i = blockIdx.x * blockDim.x + threadIdx.x; i < n;
         i += gridDim.x * blockDim.x) {
        float v = X[i];
        float gl = 0.5f * v * (1.0f + erff(v * 0.70710678118654752f));
        __nv_bfloat16 h = __float2bfloat16(gl);
        hi[i] = h;
        lo[i] = __float2bfloat16(gl - __bfloat162float(h));
    }
}

// ------------- weight transpose-convert: [K,N] -> [N,K] bf16 hi/lo ----------
__global__ void wtrans_kernel(const float* __restrict__ W,
                              __nv_bfloat16* __restrict__ hi,
                              __nv_bfloat16* __restrict__ lo, int K, int N) {
    __shared__ float t[64][65];
    const int n0 = blockIdx.x * 64, k0 = blockIdx.y * 64;
    const int tx = threadIdx.x, ty = threadIdx.y;
#pragma unroll
    for (int r = ty; r < 64; r += 4)
        t[r][tx] = W[(size_t)(k0 + r) * N + n0 + tx];
    __syncthreads();
#pragma unroll
    for (int r = ty; r < 64; r += 4) {
        float v = t[tx][r];
        size_t o = (size_t)(n0 + r) * K + k0 + tx;
        __nv_bfloat16 h = __float2bfloat16(v);
        hi[o] = h;
        lo[o] = __float2bfloat16(v - __bfloat162float(h));
    }
}

// ---------- g-folded weight transpose: [K,N] -> [N,K] single fp16 -----------
__global__ void wtrans16_kernel(const float* __restrict__ W,
                                const float* __restrict__ gvec,
                                __half* __restrict__ out, int K, int N) {
    __shared__ float t[64][65];
    const int n0 = blockIdx.x * 64, k0 = blockIdx.y * 64;
    const int tx = threadIdx.x, ty = threadIdx.y;
#pragma unroll
    for (int r = ty; r < 64; r += 4)
        t[r][tx] = W[(size_t)(k0 + r) * N + n0 + tx];
    __syncthreads();
    const float gk = gvec[k0 + tx];
#pragma unroll
    for (int r = ty; r < 64; r += 4)
        out[(size_t)(n0 + r) * K + k0 + tx] = __float2half(t[tx][r] * gk);
}

// ------------- bias rows (both layers): bvec[l][n] = sum_k b[l][k]*Wkv[l][k][n]
__global__ void bvec_kernel(const float* __restrict__ Wkv,
                            const float* __restrict__ ln_x_b,
                            float* __restrict__ out) {
    const int layer = blockIdx.x >> 6;
    const int n0 = (blockIdx.x & 63) * 32;
    const float* W = Wkv + (size_t)layer * DIMM * 2048;
    const float* b = ln_x_b + layer * DIMM;
    const int tx = threadIdx.x, ty = threadIdx.y;
    float acc = 0.f;
    for (int k = ty; k < DIMM; k += 8)
        acc += b[k] * W[(size_t)k * 2048 + n0 + tx];
    __shared__ float red[8][33];
    red[ty][tx] = acc;
    __syncthreads();
    if (ty == 0) {
        float s = 0.f;
#pragma unroll
        for (int r = 0; r < 8; r++) s += red[r][tx];
        out[layer * 2048 + n0 + tx] = s;
    }
}

// -------------------- bf16 3-term HMMA GEMM (latent side) -------------------
#define TG_SMEM 98304

__device__ __forceinline__ void tg_load_stage32(
    uint32_t sb, const __nv_bfloat16* a_hi, const __nv_bfloat16* a_lo,
    const __nv_bfloat16* b_hi, const __nv_bfloat16* b_lo,
    int m0, int n0, int kc, int K, int tid) {
#pragma unroll
    for (int i = 0; i < 2; i++) {
        int idx = tid + i * 256;
        int r = idx >> 2, g = idx & 3;
        uint32_t off = (uint32_t)(r * 64 + ((g ^ (r & 3)) * 16));
        size_t ar = (size_t)(m0 + r) * K + kc + g * 8;
        size_t br = (size_t)(n0 + r) * K + kc + g * 8;
        cp16(sb + off,         a_hi + ar);
        cp16(sb + 8192 + off,  a_lo + ar);
        cp16(sb + 16384 + off, b_hi + br);
        cp16(sb + 24576 + off, b_lo + br);
    }
}

template <int MODE>
__global__ __launch_bounds__(256, 2)
void tgemm_kernel(const __nv_bfloat16* __restrict__ a_hi,
                  const __nv_bfloat16* __restrict__ a_lo,
                  const __nv_bfloat16* __restrict__ b_hi,
                  const __nv_bfloat16* __restrict__ b_lo,
                  float* __restrict__ C,
                  const float* __restrict__ bias,
                  const float* __restrict__ res,
                  int M, int N, int K) {
    extern __shared__ __align__(128) char dsm[];
    const uint32_t sbase = smem_u32(dsm);

    const int tid = threadIdx.x;
    const int lane = tid & 31;
    const int wid = tid >> 5;
    const int wm = wid >> 2;
    const int wn = wid & 3;
    const int m0 = blockIdx.y * 128;
    const int n0 = blockIdx.x * 128;

    const int lr = (lane & 7) + ((lane >> 3) & 1) * 8;
    const int gl = lane >> 4;
    const int rA = wm * 64 + lr;
    const int rB = wn * 32 + lr;
    const uint32_t baseA = (uint32_t)(rA * 64);
    const uint32_t baseB = (uint32_t)(rB * 64);
    const int xA = rA & 3, xB = rB & 3;

    float acc[4][4][4];
#pragma unroll
    for (int i = 0; i < 4; i++)
#pragma unroll
        for (int j = 0; j < 4; j++)
#pragma unroll
            for (int t = 0; t < 4; t++) acc[i][j][t] = 0.f;

    const int nc = K >> 5;
    tg_load_stage32(sbase, a_hi, a_lo, b_hi, b_lo, m0, n0, 0, K, tid);
    CP_COMMIT();
    tg_load_stage32(sbase + 32768, a_hi, a_lo, b_hi, b_lo, m0, n0, 32, K, tid);
    CP_COMMIT();
    CP_WAIT1();
    __syncthreads();

    int stage = 0;
    for (int c = 0; c < nc; c++) {
        const uint32_t sb = sbase + stage * 32768;
        if (c + 2 < nc) {
            int ns = stage + 2; if (ns >= 3) ns -= 3;
            tg_load_stage32(sbase + ns * 32768, a_hi, a_lo, b_hi, b_lo,
                            m0, n0, (c + 2) << 5, K, tid);
        }
        CP_COMMIT();
#pragma unroll
        for (int ks = 0; ks < 2; ks++) {
            const uint32_t kgA = (uint32_t)(((ks * 2 + gl) ^ xA) * 16);
            const uint32_t kgB = (uint32_t)(((ks * 2 + gl) ^ xB) * 16);
            uint32_t fa[4][4], fbh[2][4], fbl[2][4];
#pragma unroll
            for (int i = 0; i < 4; i++)
                ldsm_x4(fa[i][0], fa[i][1], fa[i][2], fa[i][3],
                        sb + baseA + i * 1024 + kgA);
#pragma unroll
            for (int jj = 0; jj < 2; jj++) {
                uint32_t bd = sb + 16384 + baseB + jj * 1024 + kgB;
                ldsm_x4(fbh[jj][0], fbh[jj][1], fbh[jj][2], fbh[jj][3], bd);
                ldsm_x4(fbl[jj][0], fbl[jj][1], fbl[jj][2], fbl[jj][3], bd + 8192);
            }
#pragma unroll
            for (int i = 0; i < 4; i++)
#pragma unroll
                for (int j = 0; j < 4; j++) {
                    const int jj = j >> 1, sel = j & 1;
                    mma_bf16(acc[i][j][0], acc[i][j][1], acc[i][j][2], acc[i][j][3],
                             fa[i][0], fa[i][1], fa[i][2], fa[i][3],
                             fbh[jj][sel], fbh[jj][sel + 2]);
                    mma_bf16(acc[i][j][0], acc[i][j][1], acc[i][j][2], acc[i][j][3],
                             fa[i][0], fa[i][1], fa[i][2], fa[i][3],
                             fbl[jj][sel], fbl[jj][sel + 2]);
                }
#pragma unroll
            for (int i = 0; i < 4; i++)
                ldsm_x4(fa[i][0], fa[i][1], fa[i][2], fa[i][3],
                        sb + 8192 + baseA + i * 1024 + kgA);
#pragma unroll
            for (int i = 0; i < 4; i++)
#pragma unroll
                for (int j = 0; j < 4; j++) {
                    const int jj = j >> 1, sel = j & 1;
                    mma_bf16(acc[i][j][0], acc[i][j][1], acc[i][j][2], acc[i][j][3],
                             fa[i][0], fa[i][1], fa[i][2], fa[i][3],
                             fbh[jj][sel], fbh[jj][sel + 2]);
                }
        }
        CP_WAIT1();
        __syncthreads();
        stage++; if (stage >= 3) stage = 0;
    }

#pragma unroll
    for (int i = 0; i < 4; i++) {
        const int row = m0 + wm * 64 + i * 16 + (lane >> 2);
#pragma unroll
        for (int j = 0; j < 4; j++) {
            const int col = n0 + wn * 32 + j * 8 + (lane & 3) * 2;
            float c0 = acc[i][j][0], c1 = acc[i][j][1];
            float c2 = acc[i][j][2], c3 = acc[i][j][3];
            if (MODE >= 1) {
                float b0 = bias[col], b1 = bias[col + 1];
                c0 += b0; c1 += b1; c2 += b0; c3 += b1;
            }
            if (MODE == 2) {
                const float* r0 = res + (size_t)row * N + col;
                const float* r1 = res + (size_t)(row + 8) * N + col;
                c0 += r0[0]; c1 += r0[1]; c2 += r1[0]; c3 += r1[1];
            }
            *(float2*)(C + (size_t)row * N + col)       = make_float2(c0, c1);
            *(float2*)(C + (size_t)(row + 8) * N + col) = make_float2(c2, c3);
        }
    }
}

// ----------------- fp16 2-term HMMA GEMM (big ctx-KV GEMM) ------------------
// A = z fp16 exact 2-split (hi+lo), B = g-folded weights single fp16.
// Stage: Ah 8K | Al 8K | B 8K = 24KB, 3 stages = 72KB, 2 CTAs/SM.
#define TG16_SMEM 73728

__device__ __forceinline__ void tg16_load_stage(
    uint32_t sb, const __half* a_hi, const __half* a_lo, const __half* b,
    int m0, int n0, int kc, int K, int tid) {
#pragma unroll
    for (int i = 0; i < 2; i++) {
        int idx = tid + i * 256;
        int r = idx >> 2, g = idx & 3;
        uint32_t off = (uint32_t)(r * 64 + ((g ^ (r & 3)) * 16));
        size_t ar = (size_t)(m0 + r) * K + kc + g * 8;
        size_t br = (size_t)(n0 + r) * K + kc + g * 8;
        cp16(sb + off,         a_hi + ar);
        cp16(sb + 8192 + off,  a_lo + ar);
        cp16(sb + 16384 + off, b + br);
    }
}

__global__ __launch_bounds__(256, 2)
void tgemm16_kernel(const __half* __restrict__ a_hi,
                    const __half* __restrict__ a_lo,
                    const __half* __restrict__ b,
                    float* __restrict__ C,
                    const float* __restrict__ bias,
                    int M, int N, int K) {
    extern __shared__ __align__(128) char dsm[];
    const uint32_t sbase = smem_u32(dsm);

    const int tid = threadIdx.x;
    const int lane = tid & 31;
    const int wid = tid >> 5;
    const int wm = wid >> 2;
    const int wn = wid & 3;
    const int m0 = blockIdx.y * 128;
    const int n0 = blockIdx.x * 128;

    const int lr = (lane & 7) + ((lane >> 3) & 1) * 8;
    const int gl = lane >> 4;
    const int rA = wm * 64 + lr;
    const int rB = wn * 32 + lr;
    const uint32_t baseA = (uint32_t)(rA * 64);
    const uint32_t baseB = (uint32_t)(rB * 64);
    const int xA = rA & 3, xB = rB & 3;

    float acc[4][4][4];
#pragma unroll
    for (int i = 0; i < 4; i++)
#pragma unroll
        for (int j = 0; j < 4; j++)
#pragma unroll
            for (int t = 0; t < 4; t++) acc[i][j][t] = 0.f;

    const int nc = K >> 5;
    tg16_load_stage(sbase, a_hi, a_lo, b, m0, n0, 0, K, tid);
    CP_COMMIT();
    tg16_load_stage(sbase + 24576, a_hi, a_lo, b, m0, n0, 32, K, tid);
    CP_COMMIT();
    CP_WAIT1();
    __syncthreads();

    int stage = 0;
    for (int c = 0; c < nc; c++) {
        const uint32_t sb = sbase + stage * 24576;
        if (c + 2 < nc) {
            int ns = stage + 2; if (ns >= 3) ns -= 3;
            tg16_load_stage(sbase + ns * 24576, a_hi, a_lo, b,
                            m0, n0, (c + 2) << 5, K, tid);
        }
        CP_COMMIT();
#pragma unroll
        for (int ks = 0; ks < 2; ks++) {
            const uint32_t kgA = (uint32_t)(((ks * 2 + gl) ^ xA) * 16);
            const uint32_t kgB = (uint32_t)(((ks * 2 + gl) ^ xB) * 16);
            uint32_t ah[4][4], al[4][4], fb[2][4];
#pragma unroll
            for (int i = 0; i < 4; i++) {
                uint32_t ad = sb + baseA + i * 1024 + kgA;
                ldsm_x4(ah[i][0], ah[i][1], ah[i][2], ah[i][3], ad);
                ldsm_x4(al[i][0], al[i][1], al[i][2], al[i][3], ad + 8192);
            }
#pragma unroll
            for (int jj = 0; jj < 2; jj++)
                ldsm_x4(fb[jj][0], fb[jj][1], fb[jj][2], fb[jj][3],
                        sb + 16384 + baseB + jj * 1024 + kgB);
#pragma unroll
            for (int i = 0; i < 4; i++)
#pragma unroll
                for (int j = 0; j < 4; j++) {
                    const int jj = j >> 1, sel = j & 1;
                    mma_f16(acc[i][j][0], acc[i][j][1], acc[i][j][2], acc[i][j][3],
                            ah[i][0], ah[i][1], ah[i][2], ah[i][3],
                            fb[jj][sel], fb[jj][sel + 2]);
                    mma_f16(acc[i][j][0], acc[i][j][1], acc[i][j][2], acc[i][j][3],
                            al[i][0], al[i][1], al[i][2], al[i][3],
                            fb[jj][sel], fb[jj][sel + 2]);
                }
        }
        CP_WAIT1();
        __syncthreads();
        stage++; if (stage >= 3) stage = 0;
    }

#pragma unroll
    for (int i = 0; i < 4; i++) {
        const int row = m0 + wm * 64 + i * 16 + (lane >> 2);
#pragma unroll
        for (int j = 0; j < 4; j++) {
            const int col = n0 + wn * 32 + j * 8 + (lane & 3) * 2;
            float b0 = bias[col], b1 = bias[col + 1];
            *(float2*)(C + (size_t)row * N + col) =
                make_float2(acc[i][j][0] + b0, acc[i][j][1] + b1);
            *(float2*)(C + (size_t)(row + 8) * N + col) =
                make_float2(acc[i][j][2] + b0, acc[i][j][3] + b1);
        }
    }
}

// ---------------------- flash attention (HMMA, split-KV) --------------------
#define ATT_SMEM 49152

__global__ __launch_bounds__(128, 1)
void attn_kernel(const float* __restrict__ qkv,
                 const float* __restrict__ kvc_l,
                 const float* __restrict__ qn_g,
                 const float* __restrict__ kn_g,
                 float* __restrict__ po,
                 float2* __restrict__ pml) {
    extern __shared__ __align__(128) char asmem[];
    const uint32_t sq = smem_u32(asmem);
    const uint32_t sk = sq + 16384;
    const uint32_t sv = sq + 32768;

    const int h = blockIdx.x, b = blockIdx.y, split = blockIdx.z;
    const int tid = threadIdx.x, lane = tid & 31, w = tid >> 5;

    {
        const int qi = tid >> 1, half = tid & 1;
        const float* qrow = qkv + (size_t)(b * NL + qi) * QKV_STRIDE + h * DH + half * 32;
        float v[32]; float ss = 0.f;
#pragma unroll
        for (int i = 0; i < 32; i += 4) {
            float4 t = *(const float4*)(qrow + i);
            v[i] = t.x; v[i+1] = t.y; v[i+2] = t.z; v[i+3] = t.w;
            ss += t.x*t.x + t.y*t.y + t.z*t.z + t.w*t.w;
        }
        ss += __shfl_xor_sync(0xffffffffu, ss, 1);
        float sc = (1.0f / fmaxf(sqrtf(ss) * 0.125f, 1e-8f)) * 0.125f;
#pragma unroll
        for (int i = 0; i < 32; i++) v[i] *= sc * qn_g[half * 32 + i];
#pragma unroll
        for (int j = 0; j < 4; j++) {
            uint32_t ph[4], pl[4];
#pragma unroll
            for (int t = 0; t < 4; t++) {
                ph[t] = pk_hi(v[j*8 + t*2], v[j*8 + t*2 + 1]);
                pl[t] = pk_lo(v[j*8 + t*2], v[j*8 + t*2 + 1], ph[t]);
            }
            uint32_t off = (uint32_t)(qi * 128 + (((half * 4 + j) ^ (qi & 7)) * 16));
            *(uint4*)(asmem + off) = make_uint4(ph[0], ph[1], ph[2], ph[3]);
            *(uint4*)(asmem + 8192 + off) = make_uint4(pl[0], pl[1], pl[2], pl[3]);
        }
    }
    __syncthreads();

    const int lr = (lane & 7) + ((lane >> 3) & 1) * 8;
    const int gl = lane >> 4;
    const int rQ = w * 16 + lr;
    uint32_t qah[4][4], qal[4][4];
#pragma unroll
    for (int kt = 0; kt < 4; kt++) {
        uint32_t ad = sq + (uint32_t)(rQ * 128 + (((kt * 2 + gl) ^ (rQ & 7)) * 16));
        ldsm_x4(qah[kt][0], qah[kt][1], qah[kt][2], qah[kt][3], ad);
        ldsm_x4(qal[kt][0], qal[kt][1], qal[kt][2], qal[kt][3], ad + 8192);
    }

    float m0 = -INFINITY, m1 = -INFINITY, l0 = 0.f, l1 = 0.f;
    float o[8][4];
#pragma unroll
    for (int g = 0; g < 8; g++)
#pragma unroll
        for (int t = 0; t < 4; t++) o[g][t] = 0.f;

    const int nchunks = (split < 8) ? 8 : 1;
    for (int cc = 0; cc < nchunks; cc++) {
        {
            const int key = tid >> 1, half = tid & 1;
            const int j = split * 512 + cc * 64 + key;
            const float* base = (split < 8)
                ? kvc_l + (size_t)(b * SS + j) * KVC_STRIDE
                : qkv + (size_t)(b * NL + (j - SS)) * QKV_STRIDE + 1024;
            const float* kp = base + h * DH + half * 32;
            float v[32]; float ss = 0.f;
#pragma unroll
            for (int i = 0; i < 32; i += 4) {
                float4 t = *(const float4*)(kp + i);
                v[i] = t.x; v[i+1] = t.y; v[i+2] = t.z; v[i+3] = t.w;
                ss += t.x*t.x + t.y*t.y + t.z*t.z + t.w*t.w;
            }
            ss += __shfl_xor_sync(0xffffffffu, ss, 1);
            float inv = 1.0f / fmaxf(sqrtf(ss) * 0.125f, 1e-8f);
#pragma unroll
            for (int i = 0; i < 32; i++) v[i] *= inv * kn_g[half * 32 + i];
#pragma unroll
            for (int jg = 0; jg < 4; jg++) {
                uint32_t ph[4], pl[4];
#pragma unroll
                for (int t = 0; t < 4; t++) {
                    ph[t] = pk_hi(v[jg*8 + t*2], v[jg*8 + t*2 + 1]);
                    pl[t] = pk_lo(v[jg*8 + t*2], v[jg*8 + t*2 + 1], ph[t]);
                }
                uint32_t off = (uint32_t)(key * 128 + (((half * 4 + jg) ^ (key & 7)) * 16));
                *(uint4*)(asmem + 16384 + off) = make_uint4(ph[0], ph[1], ph[2], ph[3]);
                *(uint4*)(asmem + 24576 + off) = make_uint4(pl[0], pl[1], pl[2], pl[3]);
            }
            const float* vp = base + 1024 + h * DH + half * 32;
#pragma unroll
            for (int i = 0; i < 32; i++) {
                float vv = vp[i];
                int d = half * 32 + i;
                __nv_bfloat16 hh = __float2bfloat16(vv);
                __nv_bfloat16 ll = __float2bfloat16(vv - __bfloat162float(hh));
                uint32_t off = (uint32_t)(d * 128 + (((key >> 3) ^ (d & 7)) * 16)
                                          + (key & 7) * 2);
                *(__nv_bfloat16*)(asmem + 32768 + off) = hh;
                *(__nv_bfloat16*)(asmem + 40960 + off) = ll;
            }
        }
        __syncthreads();

        float s[8][4];
#pragma unroll
        for (int g = 0; g < 8; g++)
#pragma unroll
            for (int t = 0; t < 4; t++) s[g][t] = 0.f;
#pragma unroll
        for (int kt = 0; kt < 4; kt++) {
#pragma unroll
            for (int np = 0; np < 4; np++) {
                int rw = np * 16 + lr;
                uint32_t bd = sk + (uint32_t)(rw * 128 + (((kt*2+gl) ^ (rw & 7)) * 16));
                uint32_t hb[4], lb[4];
                ldsm_x4(hb[0], hb[1], hb[2], hb[3], bd);
                ldsm_x4(lb[0], lb[1], lb[2], lb[3], bd + 8192);
#pragma unroll
                for (int sub = 0; sub < 2; sub++) {
                    int ng = np * 2 + sub;
                    mma_bf16(s[ng][0], s[ng][1], s[ng][2], s[ng][3],
                             qah[kt][0], qah[kt][1], qah[kt][2], qah[kt][3],
                             hb[sub], hb[sub + 2]);
                    mma_bf16(s[ng][0], s[ng][1], s[ng][2], s[ng][3],
                             qah[kt][0], qah[kt][1], qah[kt][2], qah[kt][3],
                             lb[sub], lb[sub + 2]);
                    mma_bf16(s[ng][0], s[ng][1], s[ng][2], s[ng][3],
                             qal[kt][0], qal[kt][1], qal[kt][2], qal[kt][3],
                             hb[sub], hb[sub + 2]);
                }
            }
        }

        float cm0 = -INFINITY, cm1 = -INFINITY;
#pragma unroll
        for (int g = 0; g < 8; g++) {
            cm0 = fmaxf(cm0, fmaxf(s[g][0], s[g][1]));
            cm1 = fmaxf(cm1, fmaxf(s[g][2], s[g][3]));
        }
        cm0 = fmaxf(cm0, __shfl_xor_sync(0xffffffffu, cm0, 1));
        cm0 = fmaxf(cm0, __shfl_xor_sync(0xffffffffu, cm0, 2));
        cm1 = fmaxf(cm1, __shfl_xor_sync(0xffffffffu, cm1, 1));
        cm1 = fmaxf(cm1, __shfl_xor_sync(0xffffffffu, cm1, 2));
        float nm0 = fmaxf(m0, cm0), nm1 = fmaxf(m1, cm1);
        float a0 = __expf(m0 - nm0), a1 = __expf(m1 - nm1);
        float p[8][4]; float ls0 = 0.f, ls1 = 0.f;
#pragma unroll
        for (int g = 0; g < 8; g++) {
            p[g][0] = __expf(s[g][0] - nm0);
            p[g][1] = __expf(s[g][1] - nm0);
            p[g][2] = __expf(s[g][2] - nm1);
            p[g][3] = __expf(s[g][3] - nm1);
            ls0 += p[g][0] + p[g][1];
            ls1 += p[g][2] + p[g][3];
        }
        ls0 += __shfl_xor_sync(0xffffffffu, ls0, 1);
        ls0 += __shfl_xor_sync(0xffffffffu, ls0, 2);
        ls1 += __shfl_xor_sync(0xffffffffu, ls1, 1);
        ls1 += __shfl_xor_sync(0xffffffffu, ls1, 2);
        l0 = l0 * a0 + ls0; l1 = l1 * a1 + ls1;
        m0 = nm0; m1 = nm1;
#pragma unroll
        for (int g = 0; g < 8; g++) {
            o[g][0] *= a0; o[g][1] *= a0; o[g][2] *= a1; o[g][3] *= a1;
        }

#pragma unroll
        for (int kt = 0; kt < 4; kt++) {
            uint32_t pah[4], pal[4];
            pah[0] = pk_hi(p[2*kt][0],   p[2*kt][1]);
            pah[1] = pk_hi(p[2*kt][2],   p[2*kt][3]);
            pah[2] = pk_hi(p[2*kt+1][0], p[2*kt+1][1]);
            pah[3] = pk_hi(p[2*kt+1][2], p[2*kt+1][3]);
            pal[0] = pk_lo(p[2*kt][0],   p[2*kt][1],   pah[0]);
            pal[1] = pk_lo(p[2*kt][2],   p[2*kt][3],   pah[1]);
            pal[2] = pk_lo(p[2*kt+1][0], p[2*kt+1][1], pah[2]);
            pal[3] = pk_lo(p[2*kt+1][2], p[2*kt+1][3], pah[3]);
#pragma unroll
            for (int np = 0; np < 4; np++) {
                int rw = np * 16 + lr;
                uint32_t bd = sv + (uint32_t)(rw * 128 + (((kt*2+gl) ^ (rw & 7)) * 16));
                uint32_t hb[4], lb[4];
                ldsm_x4(hb[0], hb[1], hb[2], hb[3], bd);
                ldsm_x4(lb[0], lb[1], lb[2], lb[3], bd + 8192);
#pragma unroll
                for (int sub = 0; sub < 2; sub++) {
                    int ng = np * 2 + sub;
                    mma_bf16(o[ng][0], o[ng][1], o[ng][2], o[ng][3],
                             pah[0], pah[1], pah[2], pah[3], hb[sub], hb[sub + 2]);
                    mma_bf16(o[ng][0], o[ng][1], o[ng][2], o[ng][3],
                             pah[0], pah[1], pah[2], pah[3], lb[sub], lb[sub + 2]);
                    mma_bf16(o[ng][0], o[ng][1], o[ng][2], o[ng][3],
                             pal[0], pal[1], pal[2], pal[3], hb[sub], hb[sub + 2]);
                }
            }
        }
        __syncthreads();
    }

    const int row0 = w * 16 + (lane >> 2);
    const size_t pob = (size_t)((b * NH + h) * NSPLIT + split) * 4096;
#pragma unroll
    for (int g = 0; g < 8; g++) {
        int d0 = g * 8 + (lane & 3) * 2;
        *(float2*)(po + pob + (size_t)row0 * 64 + d0)       = make_float2(o[g][0], o[g][1]);
        *(float2*)(po + pob + (size_t)(row0 + 8) * 64 + d0) = make_float2(o[g][2], o[g][3]);
    }
    if ((lane & 3) == 0) {
        pml[((b * NH + h) * NSPLIT + split) * 64 + row0]     = make_float2(m0, l0);
        pml[((b * NH + h) * NSPLIT + split) * 64 + row0 + 8] = make_float2(m1, l1);
    }
}

// ---- combine split-KV partials; emit bf16 hi/lo directly ----
__global__ void attn_combine(const float* __restrict__ po,
                             const float2* __restrict__ pml,
                             __nv_bfloat16* __restrict__ ao_hi,
                             __nv_bfloat16* __restrict__ ao_lo) {
    const int bh = blockIdx.x;
    const int t = threadIdx.x;
    const int q = t >> 2, quad = t & 3;
    const int b = bh >> 4, h = bh & 15;

    float2 ml[NSPLIT];
    float M = -INFINITY;
#pragma unroll
    for (int s = 0; s < NSPLIT; s++) {
        ml[s] = pml[(bh * NSPLIT + s) * 64 + q];
        M = fmaxf(M, ml[s].x);
    }
    float L = 0.f; float wgt[NSPLIT];
#pragma unroll
    for (int s = 0; s < NSPLIT; s++) {
        wgt[s] = __expf(ml[s].x - M);
        L += ml[s].y * wgt[s];
    }
    float acc[16];
#pragma unroll
    for (int i = 0; i < 16; i++) acc[i] = 0.f;
#pragma unroll
    for (int s = 0; s < NSPLIT; s++) {
        const float* base = po + (size_t)(bh * NSPLIT + s) * 4096 + q * 64 + quad * 16;
#pragma unroll
        for (int i = 0; i < 4; i++) {
            float4 v = *(const float4*)(base + i * 4);
            acc[i*4+0] += wgt[s] * v.x; acc[i*4+1] += wgt[s] * v.y;
            acc[i*4+2] += wgt[s] * v.z; acc[i*4+3] += wgt[s] * v.w;
        }
    }
    float invL = 1.0f / L;
    size_t ob = (size_t)(b * NL + q) * DIMM + h * DH + quad * 16;
#pragma unroll
    for (int i = 0; i < 4; i++) {
        bf4 hh, ll;
#pragma unroll
        for (int e = 0; e < 4; e++) {
            float v = acc[i*4+e] * invL;
            hh.v[e] = __float2bfloat16(v);
            ll.v[e] = __float2bfloat16(v - __bfloat162float(hh.v[e]));
        }
        *(bf4*)(ao_hi + ob + i * 4) = hh;
        *(bf4*)(ao_lo + ob + i * 4) = ll;
    }
}

// ------------------------------- launcher ----------------------------------
extern "C" void kernel_launch(void* const* d_in, const int* in_sizes, int n_in,
                              void* d_out, int out_size) {
    const float* x       = (const float*)d_in[0];
    const float* pos     = (const float*)d_in[2];
    const float* lat0    = (const float*)d_in[3];
    const float* ln_x_g  = (const float*)d_in[4];
    const float* ln_x_b  = (const float*)d_in[5];
    const float* ln_l_g  = (const float*)d_in[6];
    const float* ln_l_b  = (const float*)d_in[7];
    const float* qn_g    = (const float*)d_in[8];
    const float* kn_g    = (const float*)d_in[9];
    const float* Wq      = (const float*)d_in[10];
    const float* Wkv     = (const float*)d_in[11];
    const float* Wo      = (const float*)d_in[12];
    const float* bo      = (const float*)d_in[13];
    const float* ff_ln_g = (const float*)d_in[14];
    const float* ff_ln_b = (const float*)d_in[15];
    const float* W1      = (const float*)d_in[16];
    const float* b1      = (const float*)d_in[17];
    const float* W2      = (const float*)d_in[18];
    const float* b2      = (const float*)d_in[19];
    const float* fn_g    = (const float*)d_in[20];
    const float* fn_b    = (const float*)d_in[21];

    cudaFuncSetAttribute(tgemm_kernel<0>,
                         cudaFuncAttributeMaxDynamicSharedMemorySize, TG_SMEM);
    cudaFuncSetAttribute(tgemm_kernel<1>,
                         cudaFuncAttributeMaxDynamicSharedMemorySize, TG_SMEM);
    cudaFuncSetAttribute(tgemm_kernel<2>,
                         cudaFuncAttributeMaxDynamicSharedMemorySize, TG_SMEM);
    cudaFuncSetAttribute(tgemm16_kernel,
                         cudaFuncAttributeMaxDynamicSharedMemorySize, TG16_SMEM);
    cudaFuncSetAttribute(attn_kernel,
                         cudaFuncAttributeMaxDynamicSharedMemorySize, ATT_SMEM);

    float* scr = nullptr;
    cudaGetSymbolAddress((void**)&scr, g_scratch);
    float* po   = scr + OFF_PO;
    float2* pml = (float2*)(scr + OFF_PML);
    float* qkvl = scr + OFF_QKV;
    float* lat  = scr + OFF_LAT;
    float* lat2 = scr + OFF_LAT2;
    float* h1   = scr + OFF_H1;
    float* bvec = scr + OFF_BVEC;
    float* kvc  = scr + OFF_KVC;
    __half* zc_hi  = (__half*)(scr + OFF_ZC_HI);
    __half* zc_lo  = (__half*)(scr + OFF_ZC_LO);
    __half* wkvc16 = (__half*)(scr + OFF_WKVC16);
    __nv_bfloat16* lnl_hi = (__nv_bfloat16*)(scr + OFF_LNL_HI);
    __nv_bfloat16* lnl_lo = (__nv_bfloat16*)(scr + OFF_LNL_LO);
    __nv_bfloat16* ao_hi  = (__nv_bfloat16*)(scr + OFF_AO_HI);
    __nv_bfloat16* ao_lo  = (__nv_bfloat16*)(scr + OFF_AO_LO);
    __nv_bfloat16* h1_hi  = (__nv_bfloat16*)(scr + OFF_H1_HI);
    __nv_bfloat16* h1_lo  = (__nv_bfloat16*)(scr + OFF_H1_LO);

    const dim3 wb(64, 4);
    const dim3 bvb(32, 8);

    // ---- preprocessing ----
    initlat_kernel<<<ROWS_LAT, 256>>>(lat0, lat);
    lnz_kernel<<<ROWS_CTX, 256>>>(x, pos, zc_hi, zc_lo);
    for (int i = 0; i < 2; i++)
        wtrans16_kernel<<<dim3(2 * DIMM / 64, DIMM / 64), wb>>>(
            Wkv + (size_t)i * DIMM * 2 * DIMM, ln_x_g + i * DIMM,
            wkvc16 + (size_t)i * 2048 * 1024, DIMM, 2 * DIMM);
    bvec_kernel<<<128, bvb>>>(Wkv, ln_x_b, bvec);

    // ---- big ctx-KV GEMM (fp16 2-term): kvc[32768, 4096] ----
    tgemm16_kernel<<<dim3(4096 / 128, ROWS_CTX / 128), 256, TG16_SMEM>>>(
        zc_hi, zc_lo, wkvc16, kvc, bvec, ROWS_CTX, 4096, DIMM);

    // ---- latent-side weight preprocessing (bf16 hi/lo) ----
    for (int i = 0; i < 2; i++) {
        float* wl = scr + OFF_W + (size_t)i * WL_STRIDE;
        wtrans_kernel<<<dim3(DIMM / 64, DIMM / 64), wb>>>(
            Wq + (size_t)i * DIMM * DIMM,
            (__nv_bfloat16*)(wl + WO_QKV_HI),
            (__nv_bfloat16*)(wl + WO_QKV_LO), DIMM, DIMM);
        wtrans_kernel<<<dim3(2 * DIMM / 64, DIMM / 64), wb>>>(
            Wkv + (size_t)i * DIMM * 2 * DIMM,
            (__nv_bfloat16*)(wl + WO_QKV_HI) + (size_t)1024 * 1024,
            (__nv_bfloat16*)(wl + WO_QKV_LO) + (size_t)1024 * 1024,
            DIMM, 2 * DIMM);
        wtrans_kernel<<<dim3(DIMM / 64, DIMM / 64), wb>>>(
            Wo + (size_t)i * DIMM * DIMM,
            (__nv_bfloat16*)(wl + WO_WO_HI), (__nv_bfloat16*)(wl + WO_WO_LO),
            DIMM, DIMM);
        wtrans_kernel<<<dim3(HID / 64, DIMM / 64), wb>>>(
            W1 + (size_t)i * DIMM * HID,
            (__nv_bfloat16*)(wl + WO_W1_HI), (__nv_bfloat16*)(wl + WO_W1_LO),
            DIMM, HID);
        wtrans_kernel<<<dim3(DIMM / 64, HID / 64), wb>>>(
            W2 + (size_t)i * HID * DIMM,
            (__nv_bfloat16*)(wl + WO_W2_HI), (__nv_bfloat16*)(wl + WO_W2_LO),
            HID, DIMM);
    }

    for (int i = 0; i < 2; i++) {
        float* wl = scr + OFF_W + (size_t)i * WL_STRIDE;
        __nv_bfloat16* wqkv_hi = (__nv_bfloat16*)(wl + WO_QKV_HI);
        __nv_bfloat16* wqkv_lo = (__nv_bfloat16*)(wl + WO_QKV_LO);
        __nv_bfloat16* wo_hi   = (__nv_bfloat16*)(wl + WO_WO_HI);
        __nv_bfloat16* wo_lo   = (__nv_bfloat16*)(wl + WO_WO_LO);
        __nv_bfloat16* w1_hi   = (__nv_bfloat16*)(wl + WO_W1_HI);
        __nv_bfloat16* w1_lo   = (__nv_bfloat16*)(wl + WO_W1_LO);
        __nv_bfloat16* w2_hi   = (__nv_bfloat16*)(wl + WO_W2_HI);
        __nv_bfloat16* w2_lo   = (__nv_bfloat16*)(wl + WO_W2_LO);

        ln_kernel<0, 1, 1><<<ROWS_LAT, 256>>>(lat, nullptr, nullptr,
                                              lnl_hi, lnl_lo,
                                              ln_l_g + i * DIMM, ln_l_b + i * DIMM);
        tgemm_kernel<0><<<dim3(QKV_STRIDE / 128, ROWS_LAT / 128), 256, TG_SMEM>>>(
            lnl_hi, lnl_lo, wqkv_hi, wqkv_lo, qkvl, nullptr, nullptr,
            ROWS_LAT, QKV_STRIDE, DIMM);

        attn_kernel<<<dim3(NH, BB, NSPLIT), 128, ATT_SMEM>>>(
            qkvl, kvc + (size_t)i * 2048, qn_g + i * DH, kn_g + i * DH, po, pml);
        attn_combine<<<BB * NH, 256>>>(po, pml, ao_hi, ao_lo);

        tgemm_kernel<2><<<dim3(DIMM / 128, ROWS_LAT / 128), 256, TG_SMEM>>>(
            ao_hi, ao_lo, wo_hi, wo_lo, lat2, bo + i * DIMM, lat,
            ROWS_LAT, DIMM, DIMM);

        ln_kernel<0, 1, 1><<<ROWS_LAT, 256>>>(lat2, nullptr, nullptr,
                                              lnl_hi, lnl_lo,
                                              ff_ln_g + i * DIMM, ff_ln_b + i * DIMM);
        tgemm_kernel<1><<<dim3(HID / 128, ROWS_LAT / 128), 256, TG_SMEM>>>(
            lnl_hi, lnl_lo, w1_hi, w1_lo, h1, b1 + i * HID, nullptr,
            ROWS_LAT, HID, DIMM);
        gelu_cvt_kernel<<<2048, 256>>>(h1, h1_hi, h1_lo, ROWS_LAT * HID);
        tgemm_kernel<2><<<dim3(DIMM / 128, ROWS_LAT / 128), 256, TG_SMEM>>>(
            h1_hi, h1_lo, w2_hi, w2_lo, lat, b2 + i * DIMM, lat2,
            ROWS_LAT, DIMM, HID);
    }

    ln_kernel<0, 0, 1><<<ROWS_LAT, 256>>>(lat, nullptr, (float*)d_out,
                                          nullptr, nullptr, fn_g, fn_b);
}

// round 10
// speedup vs baseline: 2.5809x; 1.5758x over previous
#include <cuda_runtime.h>
#include <cuda_bf16.h>
#include <cuda_fp16.h>
#include <math.h>
#include <stdint.h>

// ---------------------------------------------------------------------------
// PerceiverResampler forward. Round 10:
//  - ctx-KV GEMM: single-term fp16 (A and B plain fp16), Kc=64
//  - latent GEMMs: fp16 2-term (A exact hi/lo fp16 split, B single fp16)
//  - attention unchanged (bf16 3-term internal)
// ---------------------------------------------------------------------------

#define BB 8
#define SS 4096
#define DIMM 1024
#define NL 64
#define NH 16
#define DH 64
#define HID 4096
#define ROWS_CTX (BB * SS)     // 32768
#define ROWS_LAT (BB * NL)     // 512
#define NSPLIT 9
#define QKV_STRIDE 3072
#define KVC_STRIDE 4096

// ------------------------- scratch (no allocations) ------------------------
#define OFF_PO      ((size_t)0)
#define OFF_PML     ((size_t)4718592)
#define OFF_QKV     ((size_t)4866048)
#define OFF_LAT     ((size_t)6963200)
#define OFF_LAT2    ((size_t)7487488)
#define OFF_H1      ((size_t)8011776)
#define OFF_LNL_HI  ((size_t)10108928)
#define OFF_LNL_LO  ((size_t)10371072)
#define OFF_AO_HI   ((size_t)10633216)
#define OFF_AO_LO   ((size_t)10895360)
#define OFF_H1_HI   ((size_t)11157504)
#define OFF_H1_LO   ((size_t)12206080)
#define OFF_BVEC    ((size_t)13254656)
#define OFF_ZC      ((size_t)13258752)     // 32768x1024 fp16 (64MB)
#define OFF_KVC     ((size_t)46813184)     // 32768x4096 f32
#define OFF_WKVC16  ((size_t)181030912)    // 2x(2048x1024) fp16
#define OFF_W       ((size_t)185225216)
#define WL_STRIDE   ((size_t)12582912)
#define WO_QKV 0
#define WO_WO  3145728
#define WO_W1  4194304
#define WO_W2  8388608
#define SCRATCH_FLOATS ((size_t)210391040)

__device__ __align__(1024) float g_scratch[SCRATCH_FLOATS];

// ------------------------------ PTX helpers --------------------------------
__device__ __forceinline__ uint32_t smem_u32(const void* p) {
    uint32_t a;
    asm("{ .reg .u64 t; cvta.to.shared.u64 t, %1; cvt.u32.u64 %0, t; }"
        : "=r"(a) : "l"(p));
    return a;
}
__device__ __forceinline__ void cp16(uint32_t saddr, const void* g) {
    asm volatile("cp.async.cg.shared.global [%0], [%1], 16;"
                 :: "r"(saddr), "l"(g));
}
#define CP_COMMIT() asm volatile("cp.async.commit_group;" ::: "memory")
#define CP_WAIT0()  asm volatile("cp.async.wait_group 0;" ::: "memory")
#define CP_WAIT1()  asm volatile("cp.async.wait_group 1;" ::: "memory")

__device__ __forceinline__ void ldsm_x4(uint32_t& r0, uint32_t& r1,
                                        uint32_t& r2, uint32_t& r3,
                                        uint32_t addr) {
    asm volatile("ldmatrix.sync.aligned.m8n8.x4.shared.b16 {%0,%1,%2,%3}, [%4];"
                 : "=r"(r0), "=r"(r1), "=r"(r2), "=r"(r3) : "r"(addr));
}
__device__ __forceinline__ void mma_bf16(float& c0, float& c1, float& c2,
                                         float& c3, uint32_t a0, uint32_t a1,
                                         uint32_t a2, uint32_t a3,
                                         uint32_t b0, uint32_t b1) {
    asm volatile(
        "mma.sync.aligned.m16n8k16.row.col.f32.bf16.bf16.f32 "
        "{%0,%1,%2,%3}, {%4,%5,%6,%7}, {%8,%9}, {%0,%1,%2,%3};"
        : "+f"(c0), "+f"(c1), "+f"(c2), "+f"(c3)
        : "r"(a0), "r"(a1), "r"(a2), "r"(a3), "r"(b0), "r"(b1));
}
__device__ __forceinline__ void mma_f16(float& c0, float& c1, float& c2,
                                        float& c3, uint32_t a0, uint32_t a1,
                                        uint32_t a2, uint32_t a3,
                                        uint32_t b0, uint32_t b1) {
    asm volatile(
        "mma.sync.aligned.m16n8k16.row.col.f32.f16.f16.f32 "
        "{%0,%1,%2,%3}, {%4,%5,%6,%7}, {%8,%9}, {%0,%1,%2,%3};"
        : "+f"(c0), "+f"(c1), "+f"(c2), "+f"(c3)
        : "r"(a0), "r"(a1), "r"(a2), "r"(a3), "r"(b0), "r"(b1));
}
__device__ __forceinline__ uint32_t pk_hi(float x, float y) {
    __nv_bfloat162 t = __floats2bfloat162_rn(x, y);
    return *reinterpret_cast<uint32_t*>(&t);
}
__device__ __forceinline__ uint32_t pk_lo(float x, float y, uint32_t hi) {
    __nv_bfloat162 h = *reinterpret_cast<__nv_bfloat162*>(&hi);
    return pk_hi(x - __bfloat162float(h.x), y - __bfloat162float(h.y));
}

// --------------------------- latent broadcast ------------------------------
__global__ void initlat_kernel(const float* __restrict__ lat0,
                               float* __restrict__ lat) {
    int row = blockIdx.x;
    int l = row % NL;
    for (int d = threadIdx.x; d < DIMM; d += blockDim.x)
        lat[(size_t)row * DIMM + d] = lat0[(size_t)l * DIMM + d];
}

// ------------------------------- LayerNorm ---------------------------------
struct __align__(8) bf4 { __nv_bfloat16 v[4]; };
struct __align__(8) hf4 { __half v[4]; };

// OUT: 0 = f32, 1 = fp16 hi/lo (exact split)
template <int OUT_F16, int AFFINE>
__global__ void ln_kernel(const float* __restrict__ X,
                          float* __restrict__ Yf,
                          __half* __restrict__ Yhi,
                          __half* __restrict__ Ylo,
                          const float* __restrict__ g,
                          const float* __restrict__ b) {
    const int row = blockIdx.x;
    const int tid = threadIdx.x;
    float4 v = ((const float4*)(X + (size_t)row * DIMM))[tid];
    float s  = v.x + v.y + v.z + v.w;
    float s2 = v.x * v.x + v.y * v.y + v.z * v.z + v.w * v.w;

    __shared__ float red[2][8];
    for (int o = 16; o; o >>= 1) {
        s  += __shfl_xor_sync(0xffffffffu, s, o);
        s2 += __shfl_xor_sync(0xffffffffu, s2, o);
    }
    int w = tid >> 5;
    if ((tid & 31) == 0) { red[0][w] = s; red[1][w] = s2; }
    __syncthreads();
    if (tid < 32) {
        s  = (tid < 8) ? red[0][tid] : 0.f;
        s2 = (tid < 8) ? red[1][tid] : 0.f;
        for (int o = 4; o; o >>= 1) {
            s  += __shfl_xor_sync(0xffffffffu, s, o);
            s2 += __shfl_xor_sync(0xffffffffu, s2, o);
        }
        if (tid == 0) { red[0][0] = s; red[1][0] = s2; }
    }
    __syncthreads();
    float mean = red[0][0] * (1.0f / DIMM);
    float var  = red[1][0] * (1.0f / DIMM) - mean * mean;
    float rstd = rsqrtf(var + 1e-5f);

    float y[4];
    if (AFFINE) {
        float4 gv = ((const float4*)g)[tid];
        float4 bv = ((const float4*)b)[tid];
        y[0] = (v.x - mean) * rstd * gv.x + bv.x;
        y[1] = (v.y - mean) * rstd * gv.y + bv.y;
        y[2] = (v.z - mean) * rstd * gv.z + bv.z;
        y[3] = (v.w - mean) * rstd * gv.w + bv.w;
    } else {
        y[0] = (v.x - mean) * rstd; y[1] = (v.y - mean) * rstd;
        y[2] = (v.z - mean) * rstd; y[3] = (v.w - mean) * rstd;
    }
    if (OUT_F16) {
        hf4 h, l;
#pragma unroll
        for (int e = 0; e < 4; e++) {
            h.v[e] = __float2half(y[e]);
            l.v[e] = __float2half(y[e] - __half2float(h.v[e]));
        }
        ((hf4*)(Yhi + (size_t)row * DIMM))[tid] = h;
        ((hf4*)(Ylo + (size_t)row * DIMM))[tid] = l;
    } else {
        ((float4*)(Yf + (size_t)row * DIMM))[tid] = make_float4(y[0], y[1], y[2], y[3]);
    }
}

// ---- ctx LN with pos add, NO affine, single fp16 output ----
__global__ void lnz_kernel(const float* __restrict__ X,
                           const float* __restrict__ pos,
                           __half* __restrict__ Y) {
    const int row = blockIdx.x;
    const int tid = threadIdx.x;
    float4 v = ((const float4*)(X + (size_t)row * DIMM))[tid];
    float4 p = ((const float4*)(pos + (size_t)(row & (SS - 1)) * DIMM))[tid];
    v.x += p.x; v.y += p.y; v.z += p.z; v.w += p.w;
    float s  = v.x + v.y + v.z + v.w;
    float s2 = v.x * v.x + v.y * v.y + v.z * v.z + v.w * v.w;

    __shared__ float red[2][8];
    for (int o = 16; o; o >>= 1) {
        s  += __shfl_xor_sync(0xffffffffu, s, o);
        s2 += __shfl_xor_sync(0xffffffffu, s2, o);
    }
    int w = tid >> 5;
    if ((tid & 31) == 0) { red[0][w] = s; red[1][w] = s2; }
    __syncthreads();
    if (tid < 32) {
        s  = (tid < 8) ? red[0][tid] : 0.f;
        s2 = (tid < 8) ? red[1][tid] : 0.f;
        for (int o = 4; o; o >>= 1) {
            s  += __shfl_xor_sync(0xffffffffu, s, o);
            s2 += __shfl_xor_sync(0xffffffffu, s2, o);
        }
        if (tid == 0) { red[0][0] = s; red[1][0] = s2; }
    }
    __syncthreads();
    float mean = red[0][0] * (1.0f / DIMM);
    float var  = red[1][0] * (1.0f / DIMM) - mean * mean;
    float rstd = rsqrtf(var + 1e-5f);

    hf4 h;
    h.v[0] = __float2half((v.x - mean) * rstd);
    h.v[1] = __float2half((v.y - mean) * rstd);
    h.v[2] = __float2half((v.z - mean) * rstd);
    h.v[3] = __float2half((v.w - mean) * rstd);
    ((hf4*)(Y + (size_t)row * DIMM))[tid] = h;
}

// ---------------------- gelu(exact) -> fp16 hi/lo --------------------------
__global__ void gelu_cvt_kernel(const float* __restrict__ X,
                                __half* __restrict__ hi,
                                __half* __restrict__ lo, int n) {
    for (int i = blockIdx.x * blockDim.x + threadIdx.x; i < n;
         i += gridDim.x * blockDim.x) {
        float v = X[i];
        float gl = 0.5f * v * (1.0f + erff(v * 0.70710678118654752f));
        __half h = __float2half(gl);
        hi[i] = h;
        lo[i] = __float2half(gl - __half2float(h));
    }
}

// ---------- weight transpose: [K,N] -> [N,K] single fp16 (opt g-fold) -------
template <int SCALED>
__global__ void wtrans16_kernel(const float* __restrict__ W,
                                const float* __restrict__ gvec,
                                __half* __restrict__ out, int K, int N) {
    __shared__ float t[64][65];
    const int n0 = blockIdx.x * 64, k0 = blockIdx.y * 64;
    const int tx = threadIdx.x, ty = threadIdx.y;
#pragma unroll
    for (int r = ty; r < 64; r += 4)
        t[r][tx] = W[(size_t)(k0 + r) * N + n0 + tx];
    __syncthreads();
    const float gk = SCALED ? gvec[k0 + tx] : 1.0f;
#pragma unroll
    for (int r = ty; r < 64; r += 4)
        out[(size_t)(n0 + r) * K + k0 + tx] = __float2half(t[tx][r] * gk);
}

// ------------- bias rows (both layers): bvec[l][n] = sum_k b[l][k]*Wkv[l][k][n]
__global__ void bvec_kernel(const float* __restrict__ Wkv,
                            const float* __restrict__ ln_x_b,
                            float* __restrict__ out) {
    const int layer = blockIdx.x >> 6;
    const int n0 = (blockIdx.x & 63) * 32;
    const float* W = Wkv + (size_t)layer * DIMM * 2048;
    const float* b = ln_x_b + layer * DIMM;
    const int tx = threadIdx.x, ty = threadIdx.y;
    float acc = 0.f;
    for (int k = ty; k < DIMM; k += 8)
        acc += b[k] * W[(size_t)k * 2048 + n0 + tx];
    __shared__ float red[8][33];
    red[ty][tx] = acc;
    __syncthreads();
    if (ty == 0) {
        float s = 0.f;
#pragma unroll
        for (int r = 0; r < 8; r++) s += red[r][tx];
        out[layer * 2048 + n0 + tx] = s;
    }
}

// ----------- fp16 2-term HMMA GEMM (latent side; A hi/lo, B single) ---------
// Kc=32, stage 24KB (Ah 8K | Al 8K | B 8K), 3 stages = 72KB, 2 CTAs/SM.
#define TG16_SMEM 73728

__device__ __forceinline__ void tg16_load_stage(
    uint32_t sb, const __half* a_hi, const __half* a_lo, const __half* b,
    int m0, int n0, int kc, int K, int tid) {
#pragma unroll
    for (int i = 0; i < 2; i++) {
        int idx = tid + i * 256;
        int r = idx >> 2, g = idx & 3;
        uint32_t off = (uint32_t)(r * 64 + ((g ^ (r & 3)) * 16));
        size_t ar = (size_t)(m0 + r) * K + kc + g * 8;
        size_t br = (size_t)(n0 + r) * K + kc + g * 8;
        cp16(sb + off,         a_hi + ar);
        cp16(sb + 8192 + off,  a_lo + ar);
        cp16(sb + 16384 + off, b + br);
    }
}

template <int MODE>
__global__ __launch_bounds__(256, 2)
void tgemm16_kernel(const __half* __restrict__ a_hi,
                    const __half* __restrict__ a_lo,
                    const __half* __restrict__ b,
                    float* __restrict__ C,
                    const float* __restrict__ bias,
                    const float* __restrict__ res,
                    int M, int N, int K) {
    extern __shared__ __align__(128) char dsm[];
    const uint32_t sbase = smem_u32(dsm);

    const int tid = threadIdx.x;
    const int lane = tid & 31;
    const int wid = tid >> 5;
    const int wm = wid >> 2;
    const int wn = wid & 3;
    const int m0 = blockIdx.y * 128;
    const int n0 = blockIdx.x * 128;

    const int lr = (lane & 7) + ((lane >> 3) & 1) * 8;
    const int gl = lane >> 4;
    const int rA = wm * 64 + lr;
    const int rB = wn * 32 + lr;
    const uint32_t baseA = (uint32_t)(rA * 64);
    const uint32_t baseB = (uint32_t)(rB * 64);
    const int xA = rA & 3, xB = rB & 3;

    float acc[4][4][4];
#pragma unroll
    for (int i = 0; i < 4; i++)
#pragma unroll
        for (int j = 0; j < 4; j++)
#pragma unroll
            for (int t = 0; t < 4; t++) acc[i][j][t] = 0.f;

    const int nc = K >> 5;
    tg16_load_stage(sbase, a_hi, a_lo, b, m0, n0, 0, K, tid);
    CP_COMMIT();
    tg16_load_stage(sbase + 24576, a_hi, a_lo, b, m0, n0, 32, K, tid);
    CP_COMMIT();
    CP_WAIT1();
    __syncthreads();

    int stage = 0;
    for (int c = 0; c < nc; c++) {
        const uint32_t sb = sbase + stage * 24576;
        if (c + 2 < nc) {
            int ns = stage + 2; if (ns >= 3) ns -= 3;
            tg16_load_stage(sbase + ns * 24576, a_hi, a_lo, b,
                            m0, n0, (c + 2) << 5, K, tid);
        }
        CP_COMMIT();
#pragma unroll
        for (int ks = 0; ks < 2; ks++) {
            const uint32_t kgA = (uint32_t)(((ks * 2 + gl) ^ xA) * 16);
            const uint32_t kgB = (uint32_t)(((ks * 2 + gl) ^ xB) * 16);
            uint32_t ah[4][4], al[4][4], fb[2][4];
#pragma unroll
            for (int i = 0; i < 4; i++) {
                uint32_t ad = sb + baseA + i * 1024 + kgA;
                ldsm_x4(ah[i][0], ah[i][1], ah[i][2], ah[i][3], ad);
                ldsm_x4(al[i][0], al[i][1], al[i][2], al[i][3], ad + 8192);
            }
#pragma unroll
            for (int jj = 0; jj < 2; jj++)
                ldsm_x4(fb[jj][0], fb[jj][1], fb[jj][2], fb[jj][3],
                        sb + 16384 + baseB + jj * 1024 + kgB);
#pragma unroll
            for (int i = 0; i < 4; i++)
#pragma unroll
                for (int j = 0; j < 4; j++) {
                    const int jj = j >> 1, sel = j & 1;
                    mma_f16(acc[i][j][0], acc[i][j][1], acc[i][j][2], acc[i][j][3],
                            ah[i][0], ah[i][1], ah[i][2], ah[i][3],
                            fb[jj][sel], fb[jj][sel + 2]);
                    mma_f16(acc[i][j][0], acc[i][j][1], acc[i][j][2], acc[i][j][3],
                            al[i][0], al[i][1], al[i][2], al[i][3],
                            fb[jj][sel], fb[jj][sel + 2]);
                }
        }
        CP_WAIT1();
        __syncthreads();
        stage++; if (stage >= 3) stage = 0;
    }

#pragma unroll
    for (int i = 0; i < 4; i++) {
        const int row = m0 + wm * 64 + i * 16 + (lane >> 2);
#pragma unroll
        for (int j = 0; j < 4; j++) {
            const int col = n0 + wn * 32 + j * 8 + (lane & 3) * 2;
            float c0 = acc[i][j][0], c1 = acc[i][j][1];
            float c2 = acc[i][j][2], c3 = acc[i][j][3];
            if (MODE >= 1) {
                float b0 = bias[col], b1 = bias[col + 1];
                c0 += b0; c1 += b1; c2 += b0; c3 += b1;
            }
            if (MODE == 2) {
                const float* r0 = res + (size_t)row * N + col;
                const float* r1 = res + (size_t)(row + 8) * N + col;
                c0 += r0[0]; c1 += r0[1]; c2 += r1[0]; c3 += r1[1];
            }
            *(float2*)(C + (size_t)row * N + col)       = make_float2(c0, c1);
            *(float2*)(C + (size_t)(row + 8) * N + col) = make_float2(c2, c3);
        }
    }
}

// -------------- fp16 single-term HMMA GEMM (big ctx-KV GEMM) ----------------
// Kc=64, 128B rows, stage 32KB (A 16K | B 16K), 3 stages = 96KB, 2 CTAs/SM.
#define TG1_SMEM 98304

__device__ __forceinline__ void tg1_load_stage(
    uint32_t sb, const __half* a, const __half* b,
    int m0, int n0, int kc, int K, int tid) {
#pragma unroll
    for (int i = 0; i < 4; i++) {
        int idx = tid + i * 256;            // 0..1023
        int r = idx >> 3, g = idx & 7;
        uint32_t off = (uint32_t)(r * 128 + ((g ^ (r & 7)) * 16));
        cp16(sb + off,         a + (size_t)(m0 + r) * K + kc + g * 8);
        cp16(sb + 16384 + off, b + (size_t)(n0 + r) * K + kc + g * 8);
    }
}

__global__ __launch_bounds__(256, 2)
void tgemm1_kernel(const __half* __restrict__ a,
                   const __half* __restrict__ b,
                   float* __restrict__ C,
                   const float* __restrict__ bias,
                   int M, int N, int K) {
    extern __shared__ __align__(128) char dsm[];
    const uint32_t sbase = smem_u32(dsm);

    const int tid = threadIdx.x;
    const int lane = tid & 31;
    const int wid = tid >> 5;
    const int wm = wid >> 2;
    const int wn = wid & 3;
    const int m0 = blockIdx.y * 128;
    const int n0 = blockIdx.x * 128;

    const int lr = (lane & 7) + ((lane >> 3) & 1) * 8;
    const int gl = lane >> 4;
    const int rA = wm * 64 + lr;
    const int rB = wn * 32 + lr;
    const uint32_t baseA = (uint32_t)(rA * 128);
    const uint32_t baseB = (uint32_t)(rB * 128);
    const int xA = rA & 7, xB = rB & 7;

    float acc[4][4][4];
#pragma unroll
    for (int i = 0; i < 4; i++)
#pragma unroll
        for (int j = 0; j < 4; j++)
#pragma unroll
            for (int t = 0; t < 4; t++) acc[i][j][t] = 0.f;

    const int nc = K >> 6;       // Kc = 64
    tg1_load_stage(sbase, a, b, m0, n0, 0, K, tid);
    CP_COMMIT();
    tg1_load_stage(sbase + 32768, a, b, m0, n0, 64, K, tid);
    CP_COMMIT();
    CP_WAIT1();
    __syncthreads();

    int stage = 0;
    for (int c = 0; c < nc; c++) {
        const uint32_t sb = sbase + stage * 32768;
        if (c + 2 < nc) {
            int ns = stage + 2; if (ns >= 3) ns -= 3;
            tg1_load_stage(sbase + ns * 32768, a, b, m0, n0,
                           (c + 2) << 6, K, tid);
        }
        CP_COMMIT();
#pragma unroll
        for (int kt = 0; kt < 4; kt++) {
            uint32_t fa[4][4], fb[2][4];
#pragma unroll
            for (int i = 0; i < 4; i++)
                ldsm_x4(fa[i][0], fa[i][1], fa[i][2], fa[i][3],
                        sb + baseA + i * 2048 +
                        (uint32_t)(((kt * 2 + gl) ^ xA) * 16));
#pragma unroll
            for (int jj = 0; jj < 2; jj++)
                ldsm_x4(fb[jj][0], fb[jj][1], fb[jj][2], fb[jj][3],
                        sb + 16384 + baseB + jj * 2048 +
                        (uint32_t)(((kt * 2 + gl) ^ xB) * 16));
#pragma unroll
            for (int i = 0; i < 4; i++)
#pragma unroll
                for (int j = 0; j < 4; j++) {
                    const int jj = j >> 1, sel = j & 1;
                    mma_f16(acc[i][j][0], acc[i][j][1], acc[i][j][2], acc[i][j][3],
                            fa[i][0], fa[i][1], fa[i][2], fa[i][3],
                            fb[jj][sel], fb[jj][sel + 2]);
                }
        }
        CP_WAIT1();
        __syncthreads();
        stage++; if (stage >= 3) stage = 0;
    }

#pragma unroll
    for (int i = 0; i < 4; i++) {
        const int row = m0 + wm * 64 + i * 16 + (lane >> 2);
#pragma unroll
        for (int j = 0; j < 4; j++) {
            const int col = n0 + wn * 32 + j * 8 + (lane & 3) * 2;
            float b0 = bias[col], b1 = bias[col + 1];
            *(float2*)(C + (size_t)row * N + col) =
                make_float2(acc[i][j][0] + b0, acc[i][j][1] + b1);
            *(float2*)(C + (size_t)(row + 8) * N + col) =
                make_float2(acc[i][j][2] + b0, acc[i][j][3] + b1);
        }
    }
}

// ---------------------- flash attention (HMMA, split-KV) --------------------
#define ATT_SMEM 49152

__global__ __launch_bounds__(128, 1)
void attn_kernel(const float* __restrict__ qkv,
                 const float* __restrict__ kvc_l,
                 const float* __restrict__ qn_g,
                 const float* __restrict__ kn_g,
                 float* __restrict__ po,
                 float2* __restrict__ pml) {
    extern __shared__ __align__(128) char asmem[];
    const uint32_t sq = smem_u32(asmem);
    const uint32_t sk = sq + 16384;
    const uint32_t sv = sq + 32768;

    const int h = blockIdx.x, b = blockIdx.y, split = blockIdx.z;
    const int tid = threadIdx.x, lane = tid & 31, w = tid >> 5;

    {
        const int qi = tid >> 1, half = tid & 1;
        const float* qrow = qkv + (size_t)(b * NL + qi) * QKV_STRIDE + h * DH + half * 32;
        float v[32]; float ss = 0.f;
#pragma unroll
        for (int i = 0; i < 32; i += 4) {
            float4 t = *(const float4*)(qrow + i);
            v[i] = t.x; v[i+1] = t.y; v[i+2] = t.z; v[i+3] = t.w;
            ss += t.x*t.x + t.y*t.y + t.z*t.z + t.w*t.w;
        }
        ss += __shfl_xor_sync(0xffffffffu, ss, 1);
        float sc = (1.0f / fmaxf(sqrtf(ss) * 0.125f, 1e-8f)) * 0.125f;
#pragma unroll
        for (int i = 0; i < 32; i++) v[i] *= sc * qn_g[half * 32 + i];
#pragma unroll
        for (int j = 0; j < 4; j++) {
            uint32_t ph[4], pl[4];
#pragma unroll
            for (int t = 0; t < 4; t++) {
                ph[t] = pk_hi(v[j*8 + t*2], v[j*8 + t*2 + 1]);
                pl[t] = pk_lo(v[j*8 + t*2], v[j*8 + t*2 + 1], ph[t]);
            }
            uint32_t off = (uint32_t)(qi * 128 + (((half * 4 + j) ^ (qi & 7)) * 16));
            *(uint4*)(asmem + off) = make_uint4(ph[0], ph[1], ph[2], ph[3]);
            *(uint4*)(asmem + 8192 + off) = make_uint4(pl[0], pl[1], pl[2], pl[3]);
        }
    }
    __syncthreads();

    const int lr = (lane & 7) + ((lane >> 3) & 1) * 8;
    const int gl = lane >> 4;
    const int rQ = w * 16 + lr;
    uint32_t qah[4][4], qal[4][4];
#pragma unroll
    for (int kt = 0; kt < 4; kt++) {
        uint32_t ad = sq + (uint32_t)(rQ * 128 + (((kt * 2 + gl) ^ (rQ & 7)) * 16));
        ldsm_x4(qah[kt][0], qah[kt][1], qah[kt][2], qah[kt][3], ad);
        ldsm_x4(qal[kt][0], qal[kt][1], qal[kt][2], qal[kt][3], ad + 8192);
    }

    float m0 = -INFINITY, m1 = -INFINITY, l0 = 0.f, l1 = 0.f;
    float o[8][4];
#pragma unroll
    for (int g = 0; g < 8; g++)
#pragma unroll
        for (int t = 0; t < 4; t++) o[g][t] = 0.f;

    const int nchunks = (split < 8) ? 8 : 1;
    for (int cc = 0; cc < nchunks; cc++) {
        {
            const int key = tid >> 1, half = tid & 1;
            const int j = split * 512 + cc * 64 + key;
            const float* base = (split < 8)
                ? kvc_l + (size_t)(b * SS + j) * KVC_STRIDE
                : qkv + (size_t)(b * NL + (j - SS)) * QKV_STRIDE + 1024;
            const float* kp = base + h * DH + half * 32;
            float v[32]; float ss = 0.f;
#pragma unroll
            for (int i = 0; i < 32; i += 4) {
                float4 t = *(const float4*)(kp + i);
                v[i] = t.x; v[i+1] = t.y; v[i+2] = t.z; v[i+3] = t.w;
                ss += t.x*t.x + t.y*t.y + t.z*t.z + t.w*t.w;
            }
            ss += __shfl_xor_sync(0xffffffffu, ss, 1);
            float inv = 1.0f / fmaxf(sqrtf(ss) * 0.125f, 1e-8f);
#pragma unroll
            for (int i = 0; i < 32; i++) v[i] *= inv * kn_g[half * 32 + i];
#pragma unroll
            for (int jg = 0; jg < 4; jg++) {
                uint32_t ph[4], pl[4];
#pragma unroll
                for (int t = 0; t < 4; t++) {
                    ph[t] = pk_hi(v[jg*8 + t*2], v[jg*8 + t*2 + 1]);
                    pl[t] = pk_lo(v[jg*8 + t*2], v[jg*8 + t*2 + 1], ph[t]);
                }
                uint32_t off = (uint32_t)(key * 128 + (((half * 4 + jg) ^ (key & 7)) * 16));
                *(uint4*)(asmem + 16384 + off) = make_uint4(ph[0], ph[1], ph[2], ph[3]);
                *(uint4*)(asmem + 24576 + off) = make_uint4(pl[0], pl[1], pl[2], pl[3]);
            }
            const float* vp = base + 1024 + h * DH + half * 32;
#pragma unroll
            for (int i = 0; i < 32; i++) {
                float vv = vp[i];
                int d = half * 32 + i;
                __nv_bfloat16 hh = __float2bfloat16(vv);
                __nv_bfloat16 ll = __float2bfloat16(vv - __bfloat162float(hh));
                uint32_t off = (uint32_t)(d * 128 + (((key >> 3) ^ (d & 7)) * 16)
                                          + (key & 7) * 2);
                *(__nv_bfloat16*)(asmem + 32768 + off) = hh;
                *(__nv_bfloat16*)(asmem + 40960 + off) = ll;
            }
        }
        __syncthreads();

        float s[8][4];
#pragma unroll
        for (int g = 0; g < 8; g++)
#pragma unroll
            for (int t = 0; t < 4; t++) s[g][t] = 0.f;
#pragma unroll
        for (int kt = 0; kt < 4; kt++) {
#pragma unroll
            for (int np = 0; np < 4; np++) {
                int rw = np * 16 + lr;
                uint32_t bd = sk + (uint32_t)(rw * 128 + (((kt*2+gl) ^ (rw & 7)) * 16));
                uint32_t hb[4], lb[4];
                ldsm_x4(hb[0], hb[1], hb[2], hb[3], bd);
                ldsm_x4(lb[0], lb[1], lb[2], lb[3], bd + 8192);
#pragma unroll
                for (int sub = 0; sub < 2; sub++) {
                    int ng = np * 2 + sub;
                    mma_bf16(s[ng][0], s[ng][1], s[ng][2], s[ng][3],
                             qah[kt][0], qah[kt][1], qah[kt][2], qah[kt][3],
                             hb[sub], hb[sub + 2]);
                    mma_bf16(s[ng][0], s[ng][1], s[ng][2], s[ng][3],
                             qah[kt][0], qah[kt][1], qah[kt][2], qah[kt][3],
                             lb[sub], lb[sub + 2]);
                    mma_bf16(s[ng][0], s[ng][1], s[ng][2], s[ng][3],
                             qal[kt][0], qal[kt][1], qal[kt][2], qal[kt][3],
                             hb[sub], hb[sub + 2]);
                }
            }
        }

        float cm0 = -INFINITY, cm1 = -INFINITY;
#pragma unroll
        for (int g = 0; g < 8; g++) {
            cm0 = fmaxf(cm0, fmaxf(s[g][0], s[g][1]));
            cm1 = fmaxf(cm1, fmaxf(s[g][2], s[g][3]));
        }
        cm0 = fmaxf(cm0, __shfl_xor_sync(0xffffffffu, cm0, 1));
        cm0 = fmaxf(cm0, __shfl_xor_sync(0xffffffffu, cm0, 2));
        cm1 = fmaxf(cm1, __shfl_xor_sync(0xffffffffu, cm1, 1));
        cm1 = fmaxf(cm1, __shfl_xor_sync(0xffffffffu, cm1, 2));
        float nm0 = fmaxf(m0, cm0), nm1 = fmaxf(m1, cm1);
        float a0 = __expf(m0 - nm0), a1 = __expf(m1 - nm1);
        float p[8][4]; float ls0 = 0.f, ls1 = 0.f;
#pragma unroll
        for (int g = 0; g < 8; g++) {
            p[g][0] = __expf(s[g][0] - nm0);
            p[g][1] = __expf(s[g][1] - nm0);
            p[g][2] = __expf(s[g][2] - nm1);
            p[g][3] = __expf(s[g][3] - nm1);
            ls0 += p[g][0] + p[g][1];
            ls1 += p[g][2] + p[g][3];
        }
        ls0 += __shfl_xor_sync(0xffffffffu, ls0, 1);
        ls0 += __shfl_xor_sync(0xffffffffu, ls0, 2);
        ls1 += __shfl_xor_sync(0xffffffffu, ls1, 1);
        ls1 += __shfl_xor_sync(0xffffffffu, ls1, 2);
        l0 = l0 * a0 + ls0; l1 = l1 * a1 + ls1;
        m0 = nm0; m1 = nm1;
#pragma unroll
        for (int g = 0; g < 8; g++) {
            o[g][0] *= a0; o[g][1] *= a0; o[g][2] *= a1; o[g][3] *= a1;
        }

#pragma unroll
        for (int kt = 0; kt < 4; kt++) {
            uint32_t pah[4], pal[4];
            pah[0] = pk_hi(p[2*kt][0],   p[2*kt][1]);
            pah[1] = pk_hi(p[2*kt][2],   p[2*kt][3]);
            pah[2] = pk_hi(p[2*kt+1][0], p[2*kt+1][1]);
            pah[3] = pk_hi(p[2*kt+1][2], p[2*kt+1][3]);
            pal[0] = pk_lo(p[2*kt][0],   p[2*kt][1],   pah[0]);
            pal[1] = pk_lo(p[2*kt][2],   p[2*kt][3],   pah[1]);
            pal[2] = pk_lo(p[2*kt+1][0], p[2*kt+1][1], pah[2]);
            pal[3] = pk_lo(p[2*kt+1][2], p[2*kt+1][3], pah[3]);
#pragma unroll
            for (int np = 0; np < 4; np++) {
                int rw = np * 16 + lr;
                uint32_t bd = sv + (uint32_t)(rw * 128 + (((kt*2+gl) ^ (rw & 7)) * 16));
                uint32_t hb[4], lb[4];
                ldsm_x4(hb[0], hb[1], hb[2], hb[3], bd);
                ldsm_x4(lb[0], lb[1], lb[2], lb[3], bd + 8192);
#pragma unroll
                for (int sub = 0; sub < 2; sub++) {
                    int ng = np * 2 + sub;
                    mma_bf16(o[ng][0], o[ng][1], o[ng][2], o[ng][3],
                             pah[0], pah[1], pah[2], pah[3], hb[sub], hb[sub + 2]);
                    mma_bf16(o[ng][0], o[ng][1], o[ng][2], o[ng][3],
                             pah[0], pah[1], pah[2], pah[3], lb[sub], lb[sub + 2]);
                    mma_bf16(o[ng][0], o[ng][1], o[ng][2], o[ng][3],
                             pal[0], pal[1], pal[2], pal[3], hb[sub], hb[sub + 2]);
                }
            }
        }
        __syncthreads();
    }

    const int row0 = w * 16 + (lane >> 2);
    const size_t pob = (size_t)((b * NH + h) * NSPLIT + split) * 4096;
#pragma unroll
    for (int g = 0; g < 8; g++) {
        int d0 = g * 8 + (lane & 3) * 2;
        *(float2*)(po + pob + (size_t)row0 * 64 + d0)       = make_float2(o[g][0], o[g][1]);
        *(float2*)(po + pob + (size_t)(row0 + 8) * 64 + d0) = make_float2(o[g][2], o[g][3]);
    }
    if ((lane & 3) == 0) {
        pml[((b * NH + h) * NSPLIT + split) * 64 + row0]     = make_float2(m0, l0);
        pml[((b * NH + h) * NSPLIT + split) * 64 + row0 + 8] = make_float2(m1, l1);
    }
}

// ---- combine split-KV partials; emit fp16 hi/lo directly ----
__global__ void attn_combine(const float* __restrict__ po,
                             const float2* __restrict__ pml,
                             __half* __restrict__ ao_hi,
                             __half* __restrict__ ao_lo) {
    const int bh = blockIdx.x;
    const int t = threadIdx.x;
    const int q = t >> 2, quad = t & 3;
    const int b = bh >> 4, h = bh & 15;

    float2 ml[NSPLIT];
    float M = -INFINITY;
#pragma unroll
    for (int s = 0; s < NSPLIT; s++) {
        ml[s] = pml[(bh * NSPLIT + s) * 64 + q];
        M = fmaxf(M, ml[s].x);
    }
    float L = 0.f; float wgt[NSPLIT];
#pragma unroll
    for (int s = 0; s < NSPLIT; s++) {
        wgt[s] = __expf(ml[s].x - M);
        L += ml[s].y * wgt[s];
    }
    float acc[16];
#pragma unroll
    for (int i = 0; i < 16; i++) acc[i] = 0.f;
#pragma unroll
    for (int s = 0; s < NSPLIT; s++) {
        const float* base = po + (size_t)(bh * NSPLIT + s) * 4096 + q * 64 + quad * 16;
#pragma unroll
        for (int i = 0; i < 4; i++) {
            float4 v = *(const float4*)(base + i * 4);
            acc[i*4+0] += wgt[s] * v.x; acc[i*4+1] += wgt[s] * v.y;
            acc[i*4+2] += wgt[s] * v.z; acc[i*4+3] += wgt[s] * v.w;
        }
    }
    float invL = 1.0f / L;
    size_t ob = (size_t)(b * NL + q) * DIMM + h * DH + quad * 16;
#pragma unroll
    for (int i = 0; i < 4; i++) {
        hf4 hh, ll;
#pragma unroll
        for (int e = 0; e < 4; e++) {
            float v = acc[i*4+e] * invL;
            hh.v[e] = __float2half(v);
            ll.v[e] = __float2half(v - __half2float(hh.v[e]));
        }
        *(hf4*)(ao_hi + ob + i * 4) = hh;
        *(hf4*)(ao_lo + ob + i * 4) = ll;
    }
}

// ------------------------------- launcher ----------------------------------
extern "C" void kernel_launch(void* const* d_in, const int* in_sizes, int n_in,
                              void* d_out, int out_size) {
    const float* x       = (const float*)d_in[0];
    const float* pos     = (const float*)d_in[2];
    const float* lat0    = (const float*)d_in[3];
    const float* ln_x_g  = (const float*)d_in[4];
    const float* ln_x_b  = (const float*)d_in[5];
    const float* ln_l_g  = (const float*)d_in[6];
    const float* ln_l_b  = (const float*)d_in[7];
    const float* qn_g    = (const float*)d_in[8];
    const float* kn_g    = (const float*)d_in[9];
    const float* Wq      = (const float*)d_in[10];
    const float* Wkv     = (const float*)d_in[11];
    const float* Wo      = (const float*)d_in[12];
    const float* bo      = (const float*)d_in[13];
    const float* ff_ln_g = (const float*)d_in[14];
    const float* ff_ln_b = (const float*)d_in[15];
    const float* W1      = (const float*)d_in[16];
    const float* b1      = (const float*)d_in[17];
    const float* W2      = (const float*)d_in[18];
    const float* b2      = (const float*)d_in[19];
    const float* fn_g    = (const float*)d_in[20];
    const float* fn_b    = (const float*)d_in[21];

    cudaFuncSetAttribute(tgemm16_kernel<0>,
                         cudaFuncAttributeMaxDynamicSharedMemorySize, TG16_SMEM);
    cudaFuncSetAttribute(tgemm16_kernel<1>,
                         cudaFuncAttributeMaxDynamicSharedMemorySize, TG16_SMEM);
    cudaFuncSetAttribute(tgemm16_kernel<2>,
                         cudaFuncAttributeMaxDynamicSharedMemorySize, TG16_SMEM);
    cudaFuncSetAttribute(tgemm1_kernel,
                         cudaFuncAttributeMaxDynamicSharedMemorySize, TG1_SMEM);
    cudaFuncSetAttribute(attn_kernel,
                         cudaFuncAttributeMaxDynamicSharedMemorySize, ATT_SMEM);

    float* scr = nullptr;
    cudaGetSymbolAddress((void**)&scr, g_scratch);
    float* po   = scr + OFF_PO;
    float2* pml = (float2*)(scr + OFF_PML);
    float* qkvl = scr + OFF_QKV;
    float* lat  = scr + OFF_LAT;
    float* lat2 = scr + OFF_LAT2;
    float* h1   = scr + OFF_H1;
    float* bvec = scr + OFF_BVEC;
    float* kvc  = scr + OFF_KVC;
    __half* zc     = (__half*)(scr + OFF_ZC);
    __half* wkvc16 = (__half*)(scr + OFF_WKVC16);
    __half* lnl_hi = (__half*)(scr + OFF_LNL_HI);
    __half* lnl_lo = (__half*)(scr + OFF_LNL_LO);
    __half* ao_hi  = (__half*)(scr + OFF_AO_HI);
    __half* ao_lo  = (__half*)(scr + OFF_AO_LO);
    __half* h1_hi  = (__half*)(scr + OFF_H1_HI);
    __half* h1_lo  = (__half*)(scr + OFF_H1_LO);

    const dim3 wb(64, 4);
    const dim3 bvb(32, 8);

    // ---- preprocessing ----
    initlat_kernel<<<ROWS_LAT, 256>>>(lat0, lat);
    lnz_kernel<<<ROWS_CTX, 256>>>(x, pos, zc);
    for (int i = 0; i < 2; i++)
        wtrans16_kernel<1><<<dim3(2 * DIMM / 64, DIMM / 64), wb>>>(
            Wkv + (size_t)i * DIMM * 2 * DIMM, ln_x_g + i * DIMM,
            wkvc16 + (size_t)i * 2048 * 1024, DIMM, 2 * DIMM);
    bvec_kernel<<<128, bvb>>>(Wkv, ln_x_b, bvec);

    // ---- big ctx-KV GEMM (fp16 single-term): kvc[32768, 4096] ----
    tgemm1_kernel<<<dim3(4096 / 128, ROWS_CTX / 128), 256, TG1_SMEM>>>(
        zc, wkvc16, kvc, bvec, ROWS_CTX, 4096, DIMM);

    // ---- latent-side weight preprocessing (single fp16) ----
    for (int i = 0; i < 2; i++) {
        float* wl = scr + OFF_W + (size_t)i * WL_STRIDE;
        wtrans16_kernel<0><<<dim3(DIMM / 64, DIMM / 64), wb>>>(
            Wq + (size_t)i * DIMM * DIMM, nullptr,
            (__half*)(wl + WO_QKV), DIMM, DIMM);
        wtrans16_kernel<0><<<dim3(2 * DIMM / 64, DIMM / 64), wb>>>(
            Wkv + (size_t)i * DIMM * 2 * DIMM, nullptr,
            (__half*)(wl + WO_QKV) + (size_t)1024 * 1024, DIMM, 2 * DIMM);
        wtrans16_kernel<0><<<dim3(DIMM / 64, DIMM / 64), wb>>>(
            Wo + (size_t)i * DIMM * DIMM, nullptr,
            (__half*)(wl + WO_WO), DIMM, DIMM);
        wtrans16_kernel<0><<<dim3(HID / 64, DIMM / 64), wb>>>(
            W1 + (size_t)i * DIMM * HID, nullptr,
            (__half*)(wl + WO_W1), DIMM, HID);
        wtrans16_kernel<0><<<dim3(DIMM / 64, HID / 64), wb>>>(
            W2 + (size_t)i * HID * DIMM, nullptr,
            (__half*)(wl + WO_W2), HID, DIMM);
    }

    for (int i = 0; i < 2; i++) {
        float* wl = scr + OFF_W + (size_t)i * WL_STRIDE;
        __half* wqkv = (__half*)(wl + WO_QKV);
        __half* wo   = (__half*)(wl + WO_WO);
        __half* w1   = (__half*)(wl + WO_W1);
        __half* w2   = (__half*)(wl + WO_W2);

        ln_kernel<1, 1><<<ROWS_LAT, 256>>>(lat, nullptr, lnl_hi, lnl_lo,
                                           ln_l_g + i * DIMM, ln_l_b + i * DIMM);
        tgemm16_kernel<0><<<dim3(QKV_STRIDE / 128, ROWS_LAT / 128), 256, TG16_SMEM>>>(
            lnl_hi, lnl_lo, wqkv, qkvl, nullptr, nullptr,
            ROWS_LAT, QKV_STRIDE, DIMM);

        attn_kernel<<<dim3(NH, BB, NSPLIT), 128, ATT_SMEM>>>(
            qkvl, kvc + (size_t)i * 2048, qn_g + i * DH, kn_g + i * DH, po, pml);
        attn_combine<<<BB * NH, 256>>>(po, pml, ao_hi, ao_lo);

        tgemm16_kernel<2><<<dim3(DIMM / 128, ROWS_LAT / 128), 256, TG16_SMEM>>>(
            ao_hi, ao_lo, wo, lat2, bo + i * DIMM, lat,
            ROWS_LAT, DIMM, DIMM);

        ln_kernel<1, 1><<<ROWS_LAT, 256>>>(lat2, nullptr, lnl_hi, lnl_lo,
                                           ff_ln_g + i * DIMM, ff_ln_b + i * DIMM);
        tgemm16_kernel<1><<<dim3(HID / 128, ROWS_LAT / 128), 256, TG16_SMEM>>>(
            lnl_hi, lnl_lo, w1, h1, b1 + i * HID, nullptr,
            ROWS_LAT, HID, DIMM);
        gelu_cvt_kernel<<<2048, 256>>>(h1, h1_hi, h1_lo, ROWS_LAT * HID);
        tgemm16_kernel<2><<<dim3(DIMM / 128, ROWS_LAT / 128), 256, TG16_SMEM>>>(
            h1_hi, h1_lo, w2, lat, b2 + i * DIMM, lat2,
            ROWS_LAT, DIMM, HID);
    }

    ln_kernel<0, 1><<<ROWS_LAT, 256>>>(lat, (float*)d_out, nullptr, nullptr,
                                       fn_g, fn_b);
}